// round 12
// baseline (speedup 1.0000x reference)
#include <cuda_runtime.h>
#include <cuda_bf16.h>
#include <cstdint>

// ---------------------------------------------------------------------------
// Problem dimensions (fixed by the reference)
// ---------------------------------------------------------------------------
#define BATCH    256
#define SEQL     8
#define HIDD     1024            // HID
#define D_INNER  2048
#define DSTATE   128
#define NHEADS   32
#define HEADDIM  64
#define CONV_DIM 2304            // D_INNER + 2*DSTATE
#define DPROJ    4384            // 2*D_INNER + 2*DSTATE + NHEADS
#define ROWS     (BATCH * SEQL)  // 2048

// ---------------------------------------------------------------------------
// Scratch (static device buffers; no allocation allowed in kernel_launch)
// ---------------------------------------------------------------------------
__device__ float g_a   [BATCH * 8192];    // fp32 intermediate (out1 output)
__device__ float g_zx  [ROWS  * DPROJ];   // zxbcdt (2048 x 4384)
__device__ float g_y   [ROWS  * D_INNER]; // SSM output (2048 x 2048)
__device__ float g_part[8388608];         // split-K partials

// Two ping-pong split-bf16 tiled activation buffers (max 2048x2048)
#define AMAX 4194304
__device__ __nv_bfloat16 g_p1hi[AMAX];
__device__ __nv_bfloat16 g_p1lo[AMAX];
__device__ __nv_bfloat16 g_p2hi[AMAX];
__device__ __nv_bfloat16 g_p2lo[AMAX];

// ---------------------------------------------------------------------------
// PTX helpers
// ---------------------------------------------------------------------------
__device__ __forceinline__ uint32_t smem_u32(const void* p) {
    uint32_t a;
    asm("{ .reg .u64 t; cvta.to.shared.u64 t, %1; cvt.u32.u64 %0, t; }"
        : "=r"(a) : "l"(p));
    return a;
}

#define MBARRIER_INIT(addr, count) \
    asm volatile("mbarrier.init.shared.b64 [%0], %1;" \
                 :: "r"((uint32_t)(addr)), "r"((uint32_t)(count)) : "memory")
#define MBARRIER_INVAL(addr) \
    asm volatile("mbarrier.inval.shared.b64 [%0];" \
                 :: "r"((uint32_t)(addr)) : "memory")
#define MBARRIER_EXPECT_TX(addr, bytes) \
    asm volatile("mbarrier.arrive.expect_tx.shared.b64 _, [%0], %1;" \
                 :: "r"((uint32_t)(addr)), "r"((uint32_t)(bytes)) : "memory")

#define MBARRIER_WAIT_PARITY(addr, par) do {                                   \
    uint32_t _m = (uint32_t)(addr), _p = (uint32_t)(par), _d;                  \
    asm volatile(                                                              \
        "{\n\t.reg .pred p;\n\t"                                               \
        "mbarrier.try_wait.parity.acquire.cta.shared::cta.b64 p, [%1], %2;\n\t"\
        "selp.b32 %0, 1, 0, p;\n\t}"                                           \
        : "=r"(_d) : "r"(_m), "r"(_p) : "memory");                             \
    if (!_d) {                                                                 \
        asm volatile(                                                          \
            "{\n\t.reg .pred P1;\n\t"                                          \
            "WL_%=:\n\t"                                                       \
            "mbarrier.try_wait.parity.acquire.cta.shared::cta.b64 P1, [%0], %1, 0x989680;\n\t" \
            "@P1 bra.uni WD_%=;\n\t"                                           \
            "bra.uni WL_%=;\n\t"                                               \
            "WD_%=:\n\t}"                                                      \
            :: "r"(_m), "r"(_p) : "memory");                                   \
    }                                                                          \
} while (0)

__device__ __forceinline__ void bulk_g2s(uint32_t sdst, const void* gsrc,
                                         uint32_t bytes, uint32_t mbar) {
    asm volatile(
        "cp.async.bulk.shared::cluster.global.mbarrier::complete_tx::bytes "
        "[%0], [%1], %2, [%3];"
        :: "r"(sdst), "l"(gsrc), "r"(bytes), "r"(mbar) : "memory");
}

#define LDSM4(r, addr) \
    asm volatile("ldmatrix.sync.aligned.m8n8.x4.shared.b16 {%0,%1,%2,%3}, [%4];" \
                 : "=r"((r)[0]), "=r"((r)[1]), "=r"((r)[2]), "=r"((r)[3]) \
                 : "r"(addr))

#define LDSM4T(r, addr) \
    asm volatile("ldmatrix.sync.aligned.m8n8.x4.trans.shared.b16 {%0,%1,%2,%3}, [%4];" \
                 : "=r"((r)[0]), "=r"((r)[1]), "=r"((r)[2]), "=r"((r)[3]) \
                 : "r"(addr))

#define MMA_BF16(ACCP, A0, A1, A2, A3, B0, B1)                              \
    asm volatile(                                                           \
        "mma.sync.aligned.m16n8k16.row.col.f32.bf16.bf16.f32 "              \
        "{%0,%1,%2,%3}, {%4,%5,%6,%7}, {%8,%9}, {%0,%1,%2,%3};\n"           \
        : "+f"((ACCP)[0]), "+f"((ACCP)[1]), "+f"((ACCP)[2]), "+f"((ACCP)[3])\
        : "r"(A0), "r"(A1), "r"(A2), "r"(A3), "r"(B0), "r"(B1))

// A-side split-tile address: element (row mr, col kk) of an (M,Kc) operand in
// 128x64 swizzled tiles; returns offset in halves. kk must be even.
__device__ __forceinline__ size_t tile_off(size_t mr, int kk, int kc_n) {
    int mb = (int)(mr >> 7), r = (int)(mr & 127);
    int kc = kk >> 6, kl = kk & 63;
    uint32_t off = (uint32_t)(r * 128 + kl * 2);
    uint32_t sw  = off ^ ((uint32_t)(r & 7) << 4);
    return (((size_t)mb * kc_n + kc) << 13) + (sw >> 1);
}

__device__ __forceinline__ void split_store(__nv_bfloat16* hi, __nv_bfloat16* lo,
                                            size_t base, float v0, float v1) {
    __nv_bfloat16 h0 = __float2bfloat16(v0);
    __nv_bfloat16 h1 = __float2bfloat16(v1);
    *(__nv_bfloat162*)(hi + base) = __halves2bfloat162(h0, h1);
    *(__nv_bfloat162*)(lo + base) = __halves2bfloat162(
        __float2bfloat16(v0 - __bfloat162float(h0)),
        __float2bfloat16(v1 - __bfloat162float(h1)));
}

// ---------------------------------------------------------------------------
// Activation split: A (M,K) fp32 -> hi/lo bf16 A-tiles. K = 1<<kshift.
// ---------------------------------------------------------------------------
__global__ void __launch_bounds__(256)
split_a_kernel(const float* __restrict__ A,
               __nv_bfloat16* __restrict__ hi, __nv_bfloat16* __restrict__ lo,
               int n4, int kshift)
{
    int idx = blockIdx.x * 256 + threadIdx.x;
    if (idx >= n4) return;
    const int K = 1 << kshift;
    int idx4 = idx << 2;
    size_t m = (size_t)(idx4 >> kshift);
    int k = idx4 & (K - 1);
    float4 v = ((const float4*)A)[idx];
    split_store(hi, lo, tile_off(m, k,     K >> 6), v.x, v.y);
    split_store(hi, lo, tile_off(m, k + 2, K >> 6), v.z, v.w);
}

// ---------------------------------------------------------------------------
// Split-bf16 GEMM, CTA tile 128x128, 512 threads (16 warps 4x4, warp 32x32).
// A: pre-split bf16 tiles (128x64h, swizzled), 3-stage cp.async.bulk pipeline.
// B: RAW fp32 weights (K,N) read in-kernel: LDG -> split bf16 hi/lo -> STS
//    into swizzled (K,N) 64x128 tiles (256B rows), 2-stage, LDSM.T consume.
//    (eliminates the separate weight-convert pass entirely)
// Split-K via blockIdx.z (kcn_per slabs each).
// OUT=0: C fp32 + bias/act. OUT=1: split A-tiles (K'=1<<ksh) + bias/act.
// OUT=2: fp32 partial at C + z*M*N (no bias/act).
// ---------------------------------------------------------------------------
#define A_TILE_B    16384
#define A_STAGE_B   (2 * A_TILE_B)            // Ah, Al
#define B_TILE_B    16384
#define B_STAGE_B   (2 * B_TILE_B)            // Bh, Bl
#define NSTAGE_A    3
#define NSTAGE_B    2
#define TCG_SMEM    (NSTAGE_A * A_STAGE_B + NSTAGE_B * B_STAGE_B)  // 163840

template <int ACT, int OUT>
__global__ void __launch_bounds__(512)
tc_gemm_kernel(const __nv_bfloat16* __restrict__ Ahi,
               const __nv_bfloat16* __restrict__ Alo,
               const float* __restrict__ W,      // fp32 (K,N) row-major
               const float* __restrict__ bias, float* __restrict__ C,
               __nv_bfloat16* __restrict__ Chi, __nv_bfloat16* __restrict__ Clo,
               int ksh, int kcn_per, int M, int N, int K)
{
    extern __shared__ char dsm[];
    __shared__ uint64_t mbar[NSTAGE_A];

    const uint32_t sbase = smem_u32(dsm);
    const uint32_t bbase = sbase + NSTAGE_A * A_STAGE_B;
    uint32_t mb[NSTAGE_A];
#pragma unroll
    for (int i = 0; i < NSTAGE_A; i++) mb[i] = smem_u32(&mbar[i]);

    const int tid  = threadIdx.x;
    const int lane = tid & 31;
    const int warp = tid >> 5;
    const int wm   = warp & 3;                 // 0..3 (M dir)
    const int wn   = warp >> 2;                // 0..3 (N dir)
    const int bm   = blockIdx.y * 128;
    const int bn   = blockIdx.x * 128;
    const int g    = lane >> 2;
    const int q    = lane & 3;

    // A fragment addressing (128x64h tile, non-trans LDSM)
    const int ar = lane & 15;
    const int ac = (lane >> 4) * 16;
    const uint32_t a_xor = (uint32_t)(ar & 7) << 4;
    const uint32_t a_row = (uint32_t)((wm * 32 + ar) * 128);

    // B fragment addressing ((K,N) 64x128 tile, 256B rows, LDSM.T)
    const int bk  = (lane & 7) + (((lane >> 3) & 1) << 3);   // 0..15
    const int bno = (lane >> 4) << 3;                        // 0 or 8
    const uint32_t bkb = (uint32_t)bk * 256;
    uint32_t b_cx[2];
#pragma unroll
    for (int nj = 0; nj < 2; nj++)
        b_cx[nj] = ((uint32_t)((wn * 32 + nj * 16 + bno) * 2))
                   ^ (((uint32_t)lane & 7) << 4);

    // B fill indexing: thread -> row k_f = tid>>3 (0..63), f4 chunks
    // c = (tid&7) + 8*i (i 0..3), floats [4c .. 4c+3] of the 128-wide row.
    const int k_f = tid >> 3;
    const int c_f = tid & 7;
    const uint32_t b_sw_base = (uint32_t)k_f * 256;          // byte row
    const uint32_t b_sw_xor  = ((uint32_t)k_f & 7) << 4;

    if (tid == 0)
#pragma unroll
        for (int i = 0; i < NSTAGE_A; i++) MBARRIER_INIT(mb[i], 1);
    __syncthreads();

    const int kcn = K >> 6;
    const int koff = blockIdx.z * kcn_per;
    const size_t a_tile0 = (size_t)blockIdx.y * kcn + koff;

    auto fillA = [&](int c, int s) {           // tid 0 only
        MBARRIER_EXPECT_TX(mb[s], A_STAGE_B);
        const uint32_t st = sbase + s * A_STAGE_B;
        const size_t ao = (a_tile0 + c) << 13;
        bulk_g2s(st,            Ahi + ao, A_TILE_B, mb[s]);
        bulk_g2s(st + A_TILE_B, Alo + ao, A_TILE_B, mb[s]);
    };

    float4 breg[4];
    auto ldgB = [&](int c) {                   // all threads
        const int krow = (koff + c) * 64 + k_f;
        const float* src = W + (size_t)krow * N + bn;
#pragma unroll
        for (int i = 0; i < 4; i++) {
            int n = bn + (c_f + 8 * i) * 4;
            breg[i] = (n < N) ? *(const float4*)(src + (c_f + 8 * i) * 4)
                              : make_float4(0.f, 0.f, 0.f, 0.f);
        }
    };
    auto stsB = [&](int s) {                   // split + store current breg
        const uint32_t bh = bbase + s * B_STAGE_B;
        const uint32_t bl = bh + B_TILE_B;
#pragma unroll
        for (int i = 0; i < 4; i++) {
            float4 v = breg[i];
            __nv_bfloat16 h0 = __float2bfloat16(v.x);
            __nv_bfloat16 h1 = __float2bfloat16(v.y);
            __nv_bfloat16 h2 = __float2bfloat16(v.z);
            __nv_bfloat16 h3 = __float2bfloat16(v.w);
            __nv_bfloat162 hp0 = __halves2bfloat162(h0, h1);
            __nv_bfloat162 hp1 = __halves2bfloat162(h2, h3);
            __nv_bfloat162 lp0 = __halves2bfloat162(
                __float2bfloat16(v.x - __bfloat162float(h0)),
                __float2bfloat16(v.y - __bfloat162float(h1)));
            __nv_bfloat162 lp1 = __halves2bfloat162(
                __float2bfloat16(v.z - __bfloat162float(h2)),
                __float2bfloat16(v.w - __bfloat162float(h3)));
            uint32_t cb = (uint32_t)(c_f + 8 * i) * 8;       // byte col (8B)
            uint32_t adr = b_sw_base + (cb ^ b_sw_xor);
            uint2 hv, lv;
            hv.x = *(uint32_t*)&hp0; hv.y = *(uint32_t*)&hp1;
            lv.x = *(uint32_t*)&lp0; lv.y = *(uint32_t*)&lp1;
            asm volatile("st.shared.v2.b32 [%0], {%1, %2};" ::
                         "r"(bh + adr), "r"(hv.x), "r"(hv.y));
            asm volatile("st.shared.v2.b32 [%0], {%1, %2};" ::
                         "r"(bl + adr), "r"(lv.x), "r"(lv.y));
        }
    };

    float acc[2][4][4];
#pragma unroll
    for (int mi = 0; mi < 2; mi++)
#pragma unroll
        for (int ni = 0; ni < 4; ni++)
#pragma unroll
            for (int f = 0; f < 4; f++) acc[mi][ni][f] = 0.f;

    // prologue
    ldgB(0);
    if (tid == 0)
        for (int c = 0; c < NSTAGE_A && c < kcn_per; c++) fillA(c, c);

    int ph[NSTAGE_A] = {0, 0, 0};
    int sa = 0;
    for (int c = 0; c < kcn_per; c++) {
        const int sb = c & 1;
        MBARRIER_WAIT_PARITY(mb[sa], ph[sa]);
        ph[sa] ^= 1;
        stsB(sb);
        __syncthreads();                       // B(c) visible; stages settled
        if (c + 1 < kcn_per) ldgB(c + 1);

        const uint32_t Ah = sbase + sa * A_STAGE_B;
        const uint32_t Al = Ah + A_TILE_B;
        const uint32_t Bh = bbase + sb * B_STAGE_B;
        const uint32_t Bl = Bh + B_TILE_B;

#pragma unroll
        for (int ks = 0; ks < 4; ks++) {
            uint32_t ah[2][4], al[2][4];
#pragma unroll
            for (int mi = 0; mi < 2; mi++) {
                uint32_t off = a_row + (uint32_t)(mi * 16 * 128)
                             + ((ks * 32 + ac) ^ a_xor);
                LDSM4(ah[mi], Ah + off);
                LDSM4(al[mi], Al + off);
            }
            const uint32_t bko = bkb + (uint32_t)ks * 4096;   // 16 k-rows
#pragma unroll
            for (int nj = 0; nj < 2; nj++) {
                uint32_t bh[4], bl[4];
                uint32_t off = bko + b_cx[nj];
                LDSM4T(bh, Bh + off);
                LDSM4T(bl, Bl + off);
#pragma unroll
                for (int mi = 0; mi < 2; mi++)
#pragma unroll
                    for (int hf = 0; hf < 2; hf++) {
                        float* ap = acc[mi][nj * 2 + hf];
                        MMA_BF16(ap, ah[mi][0], ah[mi][1], ah[mi][2], ah[mi][3],
                                 bh[hf * 2], bh[hf * 2 + 1]);
                        MMA_BF16(ap, ah[mi][0], ah[mi][1], ah[mi][2], ah[mi][3],
                                 bl[hf * 2], bl[hf * 2 + 1]);
                        MMA_BF16(ap, al[mi][0], al[mi][1], al[mi][2], al[mi][3],
                                 bh[hf * 2], bh[hf * 2 + 1]);
                    }
            }
        }
        __syncthreads();                       // all reads of stage sa done
        if (tid == 0 && c + NSTAGE_A < kcn_per) fillA(c + NSTAGE_A, sa);
        sa = (sa == NSTAGE_A - 1) ? 0 : sa + 1;
    }

    // ---- epilogue (N even everywhere -> pairwise guard ok)
    const int Kc = 1 << ksh;
    float* Cp = (OUT == 2) ? (C + (size_t)blockIdx.z * M * N) : C;
#pragma unroll
    for (int mi = 0; mi < 2; mi++) {
        const int m0 = bm + wm * 32 + mi * 16;
#pragma unroll
        for (int ni = 0; ni < 4; ni++) {
            const int n = bn + wn * 32 + ni * 8 + 2 * q;
            if (n >= N) continue;
            float b0 = 0.f, b1 = 0.f;
            if (OUT != 2 && bias) { b0 = bias[n]; b1 = bias[n + 1]; }
#pragma unroll
            for (int hf = 0; hf < 2; hf++) {
                const int m = m0 + g + hf * 8;
                float v0 = acc[mi][ni][hf * 2 + 0] + b0;
                float v1 = acc[mi][ni][hf * 2 + 1] + b1;
                if (OUT != 2 && ACT == 1) {
                    v0 = fmaxf(v0, 0.f); v1 = fmaxf(v1, 0.f);
                }
                if (OUT == 1) {
                    size_t flat = (size_t)m * N + n;
                    size_t mr = flat >> ksh;
                    int kk = (int)(flat & (Kc - 1));
                    split_store(Chi, Clo, tile_off(mr, kk, Kc >> 6), v0, v1);
                } else {
                    *(float2*)(Cp + (size_t)m * N + n) = make_float2(v0, v1);
                }
            }
        }
    }

    __syncthreads();
    if (tid == 0)
#pragma unroll
        for (int i = 0; i < NSTAGE_A; i++) MBARRIER_INVAL(mb[i]);
}

// ---------------------------------------------------------------------------
// Split-K reduce: sum nsplit partials, add bias, act; OUT=0 fp32, OUT=1 tiles.
// ---------------------------------------------------------------------------
template <int ACT, int OUT>
__global__ void __launch_bounds__(256)
reduce_kernel(const float* __restrict__ P, int nsplit, size_t MN,
              const float* __restrict__ bias, int nmask,
              float* __restrict__ C,
              __nv_bfloat16* __restrict__ Chi, __nv_bfloat16* __restrict__ Clo,
              int ksh)
{
    size_t f = ((size_t)blockIdx.x * 256 + threadIdx.x) * 2;
    if (f >= MN) return;
    float v0 = 0.f, v1 = 0.f;
#pragma unroll 4
    for (int z = 0; z < nsplit; z++) {
        float2 p = *(const float2*)(P + (size_t)z * MN + f);
        v0 += p.x; v1 += p.y;
    }
    if (bias) {
        int n = (int)(f & nmask);
        v0 += bias[n]; v1 += bias[n + 1];
    }
    if (ACT == 1) { v0 = fmaxf(v0, 0.f); v1 = fmaxf(v1, 0.f); }
    if (OUT == 0) {
        *(float2*)(C + f) = make_float2(v0, v1);
    } else {
        size_t mr = f >> ksh;
        int kk = (int)(f & ((1 << ksh) - 1));
        split_store(Chi, Clo, tile_off(mr, kk, (1 << ksh) >> 6), v0, v1);
    }
}

// ---------------------------------------------------------------------------
// Fused conv+SiLU+dt+scan. One CTA per (batch, head), 256 threads.
// ---------------------------------------------------------------------------
__global__ void __launch_bounds__(256)
fused_scan_kernel(const float* __restrict__ zx,
                  const float* __restrict__ conv_w,
                  const float* __restrict__ conv_b,
                  const float* __restrict__ dt_bias,
                  const float* __restrict__ A_log,
                  const float* __restrict__ Dp,
                  float* __restrict__ y)
{
    const int b = blockIdx.x;
    const int h = blockIdx.y;
    const int t = threadIdx.x;

    __shared__ float Bsh[SEQL][DSTATE];
    __shared__ float Csh[SEQL][DSTATE];
    __shared__ float xsh[SEQL][HEADDIM];
    __shared__ float dts[SEQL], dAs[SEQL];

    const float* zrow = zx + (size_t)b * SEQL * DPROJ;

    {
        const int ch  = 2048 + t;
        const int src = D_INNER + ch;
        const float w0 = conv_w[ch * 4 + 0], w1 = conv_w[ch * 4 + 1];
        const float w2 = conv_w[ch * 4 + 2], w3 = conv_w[ch * 4 + 3];
        const float bb = conv_b[ch];
        float v[SEQL];
#pragma unroll
        for (int l = 0; l < SEQL; l++) v[l] = zrow[(size_t)l * DPROJ + src];
#pragma unroll
        for (int l = 0; l < SEQL; l++) {
            float sv = bb + v[l] * w3;
            if (l >= 1) sv += v[l - 1] * w2;
            if (l >= 2) sv += v[l - 2] * w1;
            if (l >= 3) sv += v[l - 3] * w0;
            sv = sv / (1.f + expf(-sv));
            if (t < 128) Bsh[l][t] = sv;
            else         Csh[l][t - 128] = sv;
        }
    }
    if (t < HEADDIM) {
        const int ch  = h * HEADDIM + t;
        const int src = D_INNER + ch;
        const float w0 = conv_w[ch * 4 + 0], w1 = conv_w[ch * 4 + 1];
        const float w2 = conv_w[ch * 4 + 2], w3 = conv_w[ch * 4 + 3];
        const float bb = conv_b[ch];
        float v[SEQL];
#pragma unroll
        for (int l = 0; l < SEQL; l++) v[l] = zrow[(size_t)l * DPROJ + src];
#pragma unroll
        for (int l = 0; l < SEQL; l++) {
            float sv = bb + v[l] * w3;
            if (l >= 1) sv += v[l - 1] * w2;
            if (l >= 2) sv += v[l - 2] * w1;
            if (l >= 3) sv += v[l - 3] * w0;
            xsh[l][t] = sv / (1.f + expf(-sv));
        }
    }
    if (t >= 64 && t < 64 + SEQL) {
        const int l = t - 64;
        float xr = zrow[(size_t)l * DPROJ + (D_INNER + CONV_DIM) + h] + dt_bias[h];
        float dt = (xr > 20.f) ? xr : log1pf(expf(xr));
        dts[l] = dt;
        dAs[l] = expf(-expf(A_log[h]) * dt);
    }
    __syncthreads();

    const int p = t >> 2;
    const int q = t & 3;
    float st[32];
#pragma unroll
    for (int i = 0; i < 32; i++) st[i] = 0.f;
    const float Dh = Dp[h];

#pragma unroll
    for (int l = 0; l < SEQL; l++) {
        const float xv   = xsh[l][p];
        const float coef = dts[l] * xv;
        const float dAv  = dAs[l];
        float part = 0.f;
#pragma unroll
        for (int i = 0; i < 32; i++) {
            const int sidx = q + 4 * i;
            st[i] = fmaf(dAv, st[i], coef * Bsh[l][sidx]);
            part  = fmaf(st[i], Csh[l][sidx], part);
        }
        part += __shfl_down_sync(0xffffffffu, part, 2);
        part += __shfl_down_sync(0xffffffffu, part, 1);
        if (q == 0)
            y[((size_t)b * SEQL + l) * D_INNER + h * HEADDIM + p] = part + xv * Dh;
    }
}

// ---------------------------------------------------------------------------
// y = y * silu(z); y *= rsqrt(mean(y^2)+1e-5) * norm_w; emit split A-tiles.
// ---------------------------------------------------------------------------
__global__ void __launch_bounds__(256)
gated_rmsnorm_split_kernel(const float* __restrict__ ybuf,
                           const float* __restrict__ zx,
                           const float* __restrict__ norm_w,
                           __nv_bfloat16* __restrict__ hi,
                           __nv_bfloat16* __restrict__ lo)
{
    const size_t row = blockIdx.x;
    const int t = threadIdx.x;
    const int d0 = t * 8;
    const float* yb = ybuf + row * D_INNER;
    const float* zb = zx   + row * DPROJ;

    float v[8];
    float ss = 0.f;
#pragma unroll
    for (int j = 0; j < 8; j += 4) {
        float4 yv = *(const float4*)(yb + d0 + j);
        float4 zv = *(const float4*)(zb + d0 + j);
        v[j + 0] = yv.x * (zv.x / (1.f + expf(-zv.x)));
        v[j + 1] = yv.y * (zv.y / (1.f + expf(-zv.y)));
        v[j + 2] = yv.z * (zv.z / (1.f + expf(-zv.z)));
        v[j + 3] = yv.w * (zv.w / (1.f + expf(-zv.w)));
        ss = fmaf(v[j+0], v[j+0], ss); ss = fmaf(v[j+1], v[j+1], ss);
        ss = fmaf(v[j+2], v[j+2], ss); ss = fmaf(v[j+3], v[j+3], ss);
    }
#pragma unroll
    for (int o = 16; o > 0; o >>= 1)
        ss += __shfl_down_sync(0xffffffffu, ss, o);

    __shared__ float red[8];
    __shared__ float s_scale;
    if ((t & 31) == 0) red[t >> 5] = ss;
    __syncthreads();
    if (t == 0) {
        float s = 0.f;
        for (int i = 0; i < 8; i++) s += red[i];
        s_scale = rsqrtf(s / (float)D_INNER + 1e-5f);
    }
    __syncthreads();
    const float scale = s_scale;

#pragma unroll
    for (int j = 0; j < 8; j += 2) {
        int d = d0 + j;
        float v0 = v[j]     * scale * norm_w[d];
        float v1 = v[j + 1] * scale * norm_w[d + 1];
        split_store(hi, lo, tile_off(row, d, D_INNER >> 6), v0, v1);
    }
}

// ---------------------------------------------------------------------------
// Final tiny layer: out = A(256x1024) @ W(1024x2) + b. One CTA per row.
// ---------------------------------------------------------------------------
__global__ void __launch_bounds__(256)
final_kernel(const float* __restrict__ A, const float* __restrict__ W,
             const float* __restrict__ bias, float* __restrict__ out)
{
    const int m = blockIdx.x;
    const int t = threadIdx.x;
    float4 a = ((const float4*)(A + (size_t)m * 1024))[t];
    const float4 w0 = ((const float4*)W)[2 * t];
    const float4 w1 = ((const float4*)W)[2 * t + 1];
    float s0 = a.x * w0.x + a.y * w0.z + a.z * w1.x + a.w * w1.z;
    float s1 = a.x * w0.y + a.y * w0.w + a.z * w1.y + a.w * w1.w;
#pragma unroll
    for (int o = 16; o > 0; o >>= 1) {
        s0 += __shfl_down_sync(0xffffffffu, s0, o);
        s1 += __shfl_down_sync(0xffffffffu, s1, o);
    }
    __shared__ float r0[8], r1[8];
    if ((t & 31) == 0) { r0[t >> 5] = s0; r1[t >> 5] = s1; }
    __syncthreads();
    if (t == 0) {
        float a0 = 0.f, a1 = 0.f;
        for (int i = 0; i < 8; i++) { a0 += r0[i]; a1 += r1[i]; }
        out[m * 2 + 0] = a0 + bias[0];
        out[m * 2 + 1] = a1 + bias[1];
    }
}

// ---------------------------------------------------------------------------
// Host-side orchestration
// ---------------------------------------------------------------------------
struct MambaW {
    const float *in_proj, *conv_w, *conv_b, *dt_bias, *A_log, *D, *norm_w, *out_proj;
};

extern "C" void kernel_launch(void* const* d_in, const int* in_sizes, int n_in,
                              void* d_out, int out_size)
{
    const float* x      = (const float*)d_in[0];
    const float* w_in1  = (const float*)d_in[1];
    const float* b_in1  = (const float*)d_in[2];
    const float* w_in2  = (const float*)d_in[3];
    const float* b_in2  = (const float*)d_in[4];
    MambaW m1 = { (const float*)d_in[5],  (const float*)d_in[6],  (const float*)d_in[7],
                  (const float*)d_in[8],  (const float*)d_in[9],  (const float*)d_in[10],
                  (const float*)d_in[11], (const float*)d_in[12] };
    MambaW m2 = { (const float*)d_in[13], (const float*)d_in[14], (const float*)d_in[15],
                  (const float*)d_in[16], (const float*)d_in[17], (const float*)d_in[18],
                  (const float*)d_in[19], (const float*)d_in[20] };
    const float* w_out1 = (const float*)d_in[21];
    const float* b_out1 = (const float*)d_in[22];
    const float* w_out2 = (const float*)d_in[23];
    const float* b_out2 = (const float*)d_in[24];
    float* out = (float*)d_out;

    cudaFuncSetAttribute(tc_gemm_kernel<0, 0>,
                         cudaFuncAttributeMaxDynamicSharedMemorySize, TCG_SMEM);
    cudaFuncSetAttribute(tc_gemm_kernel<0, 1>,
                         cudaFuncAttributeMaxDynamicSharedMemorySize, TCG_SMEM);
    cudaFuncSetAttribute(tc_gemm_kernel<0, 2>,
                         cudaFuncAttributeMaxDynamicSharedMemorySize, TCG_SMEM);
    cudaFuncSetAttribute(tc_gemm_kernel<1, 0>,
                         cudaFuncAttributeMaxDynamicSharedMemorySize, TCG_SMEM);

    float *a, *zx, *ybuf, *part;
    __nv_bfloat16 *p1h, *p1l, *p2h, *p2l;
    cudaGetSymbolAddress((void**)&a,    g_a);
    cudaGetSymbolAddress((void**)&zx,   g_zx);
    cudaGetSymbolAddress((void**)&ybuf, g_y);
    cudaGetSymbolAddress((void**)&part, g_part);
    cudaGetSymbolAddress((void**)&p1h,  g_p1hi);
    cudaGetSymbolAddress((void**)&p1l,  g_p1lo);
    cudaGetSymbolAddress((void**)&p2h,  g_p2hi);
    cudaGetSymbolAddress((void**)&p2l,  g_p2lo);

    // ---- split x -> p1 (256 x 1024, kshift 10)
    split_a_kernel<<<(BATCH * 1024 / 4 + 255) / 256, 256>>>(x, p1h, p1l,
                                                            BATCH * 1024 / 4, 10);

    const size_t MN_256x8192  = (size_t)BATCH * 8192;
    const size_t MN_2048x1024 = (size_t)ROWS * 1024;
    const size_t MN_256x1024  = (size_t)BATCH * 1024;

    // ---- MLP in (split-K x4)
    tc_gemm_kernel<0, 2><<<dim3(64, 2, 4), 512, TCG_SMEM>>>(
        p1h, p1l, w_in1, nullptr,
        part, nullptr, nullptr, 13, 4, BATCH, 8192, 1024);
    reduce_kernel<1, 1><<<(unsigned)(MN_256x8192 / 512), 256>>>(
        part, 4, MN_256x8192, b_in1, 8191, nullptr, p2h, p2l, 13);
    tc_gemm_kernel<0, 2><<<dim3(64, 2, 4), 512, TCG_SMEM>>>(
        p2h, p2l, w_in2, nullptr,
        part, nullptr, nullptr, 10, 32, BATCH, 8192, 8192);
    reduce_kernel<0, 1><<<(unsigned)(MN_256x8192 / 512), 256>>>(
        part, 4, MN_256x8192, b_in2, 8191, nullptr, p1h, p1l, 10);

    // ---- 2x Mamba2 layers (h tiles live in p1 as (2048, 1024))
    const MambaW* layers[2] = { &m1, &m2 };
    for (int li = 0; li < 2; li++) {
        const MambaW& p = *layers[li];
        // zx = h @ in_proj (fp32 out, 560 CTAs, no split)
        tc_gemm_kernel<0, 0><<<dim3(35, 16, 1), 512, TCG_SMEM>>>(
            p1h, p1l, p.in_proj, nullptr,
            zx, nullptr, nullptr, 0, 16, ROWS, DPROJ, 1024);
        fused_scan_kernel<<<dim3(BATCH, NHEADS), 256>>>(
            zx, p.conv_w, p.conv_b, p.dt_bias, p.A_log, p.D, ybuf);
        gated_rmsnorm_split_kernel<<<ROWS, 256>>>(ybuf, zx, p.norm_w, p2h, p2l);
        // h = y @ out_proj: split-K x4, reduce -> p1 tiles
        int ksh_next = (li == 0) ? 10 : 13;
        tc_gemm_kernel<0, 2><<<dim3(8, 16, 4), 512, TCG_SMEM>>>(
            p2h, p2l, p.out_proj, nullptr,
            part, nullptr, nullptr, ksh_next, 8, ROWS, 1024, 2048);
        reduce_kernel<0, 1><<<(unsigned)(MN_2048x1024 / 512), 256>>>(
            part, 4, MN_2048x1024, nullptr, 1023, nullptr, p1h, p1l, ksh_next);
    }

    // ---- MLP out: split-K x32, reduce(relu+bias) -> fp32 a; final dot
    tc_gemm_kernel<0, 2><<<dim3(8, 2, 32), 512, TCG_SMEM>>>(
        p1h, p1l, w_out1, nullptr,
        part, nullptr, nullptr, 0, 4, BATCH, 1024, 8192);
    reduce_kernel<1, 0><<<(unsigned)(MN_256x1024 / 512), 256>>>(
        part, 32, MN_256x1024, b_out1, 1023, a, nullptr, nullptr, 0);
    final_kernel<<<BATCH, 256>>>(a, w_out2, b_out2, out);
}

// round 13
// speedup vs baseline: 1.0577x; 1.0577x over previous
#include <cuda_runtime.h>
#include <cuda_bf16.h>
#include <cstdint>

// ---------------------------------------------------------------------------
// Problem dimensions (fixed by the reference)
// ---------------------------------------------------------------------------
#define BATCH    256
#define SEQL     8
#define HIDD     1024            // HID
#define D_INNER  2048
#define DSTATE   128
#define NHEADS   32
#define HEADDIM  64
#define CONV_DIM 2304            // D_INNER + 2*DSTATE
#define DPROJ    4384            // 2*D_INNER + 2*DSTATE + NHEADS
#define ROWS     (BATCH * SEQL)  // 2048

// ---------------------------------------------------------------------------
// Scratch (static device buffers; no allocation allowed in kernel_launch)
// ---------------------------------------------------------------------------
__device__ float g_a   [BATCH * 8192];    // fp32 intermediate (out1 output)
__device__ float g_zx  [ROWS  * DPROJ];   // zxbcdt (2048 x 4384)
__device__ float g_y   [ROWS  * D_INNER]; // SSM output (2048 x 2048)
__device__ float g_part[8388608];         // split-K partials

// Two ping-pong split-bf16 tiled activation buffers (max 2048x2048)
#define AMAX 4194304
__device__ __nv_bfloat16 g_p1hi[AMAX];
__device__ __nv_bfloat16 g_p1lo[AMAX];
__device__ __nv_bfloat16 g_p2hi[AMAX];
__device__ __nv_bfloat16 g_p2lo[AMAX];

// Split-bf16 tiled weights. B tile = 64 k-rows x 256 n-cols, (K,N) layout,
// 512B per k-row, 16B chunks xor-swizzled by (k&7)<<4. One tile = 32KB
// contiguous; tile index = nb * (K/64) + kc. N padded to mult of 256.
#define OFF_WIN1     0ULL
#define OFF_WIN2     8388608ULL      // win1: 8192*1024
#define OFF_M1_INP   75497472ULL     // win2: 8192*8192
#define OFF_M2_INP   80216064ULL     // inproj: 4608*1024
#define OFF_M1_OUTP  84934656ULL
#define OFF_M2_OUTP  87031808ULL     // outproj: 1024*2048
#define OFF_WOUT1    89128960ULL
#define WT_TOTAL     97517568ULL     // + wout1: 1024*8192
__device__ __nv_bfloat16 g_whi[WT_TOTAL];
__device__ __nv_bfloat16 g_wlo[WT_TOTAL];

// ---------------------------------------------------------------------------
// PTX helpers
// ---------------------------------------------------------------------------
__device__ __forceinline__ uint32_t smem_u32(const void* p) {
    uint32_t a;
    asm("{ .reg .u64 t; cvta.to.shared.u64 t, %1; cvt.u32.u64 %0, t; }"
        : "=r"(a) : "l"(p));
    return a;
}

#define MBARRIER_INIT(addr, count) \
    asm volatile("mbarrier.init.shared.b64 [%0], %1;" \
                 :: "r"((uint32_t)(addr)), "r"((uint32_t)(count)) : "memory")
#define MBARRIER_INVAL(addr) \
    asm volatile("mbarrier.inval.shared.b64 [%0];" \
                 :: "r"((uint32_t)(addr)) : "memory")
#define MBARRIER_EXPECT_TX(addr, bytes) \
    asm volatile("mbarrier.arrive.expect_tx.shared.b64 _, [%0], %1;" \
                 :: "r"((uint32_t)(addr)), "r"((uint32_t)(bytes)) : "memory")

#define MBARRIER_WAIT_PARITY(addr, par) do {                                   \
    uint32_t _m = (uint32_t)(addr), _p = (uint32_t)(par), _d;                  \
    asm volatile(                                                              \
        "{\n\t.reg .pred p;\n\t"                                               \
        "mbarrier.try_wait.parity.acquire.cta.shared::cta.b64 p, [%1], %2;\n\t"\
        "selp.b32 %0, 1, 0, p;\n\t}"                                           \
        : "=r"(_d) : "r"(_m), "r"(_p) : "memory");                             \
    if (!_d) {                                                                 \
        asm volatile(                                                          \
            "{\n\t.reg .pred P1;\n\t"                                          \
            "WL_%=:\n\t"                                                       \
            "mbarrier.try_wait.parity.acquire.cta.shared::cta.b64 P1, [%0], %1, 0x989680;\n\t" \
            "@P1 bra.uni WD_%=;\n\t"                                           \
            "bra.uni WL_%=;\n\t"                                               \
            "WD_%=:\n\t}"                                                      \
            :: "r"(_m), "r"(_p) : "memory");                                   \
    }                                                                          \
} while (0)

__device__ __forceinline__ void bulk_g2s(uint32_t sdst, const void* gsrc,
                                         uint32_t bytes, uint32_t mbar) {
    asm volatile(
        "cp.async.bulk.shared::cluster.global.mbarrier::complete_tx::bytes "
        "[%0], [%1], %2, [%3];"
        :: "r"(sdst), "l"(gsrc), "r"(bytes), "r"(mbar) : "memory");
}

#define LDSM4(r, addr) \
    asm volatile("ldmatrix.sync.aligned.m8n8.x4.shared.b16 {%0,%1,%2,%3}, [%4];" \
                 : "=r"((r)[0]), "=r"((r)[1]), "=r"((r)[2]), "=r"((r)[3]) \
                 : "r"(addr))

#define LDSM4T(r, addr) \
    asm volatile("ldmatrix.sync.aligned.m8n8.x4.trans.shared.b16 {%0,%1,%2,%3}, [%4];" \
                 : "=r"((r)[0]), "=r"((r)[1]), "=r"((r)[2]), "=r"((r)[3]) \
                 : "r"(addr))

#define MMA_BF16(ACCP, A0, A1, A2, A3, B0, B1)                              \
    asm volatile(                                                           \
        "mma.sync.aligned.m16n8k16.row.col.f32.bf16.bf16.f32 "              \
        "{%0,%1,%2,%3}, {%4,%5,%6,%7}, {%8,%9}, {%0,%1,%2,%3};\n"           \
        : "+f"((ACCP)[0]), "+f"((ACCP)[1]), "+f"((ACCP)[2]), "+f"((ACCP)[3])\
        : "r"(A0), "r"(A1), "r"(A2), "r"(A3), "r"(B0), "r"(B1))

// A-side split-tile address: element (row mr, col kk) of an (M,Kc) operand in
// 128x64 swizzled tiles; returns offset in halves. kk must be even.
__device__ __forceinline__ size_t tile_off(size_t mr, int kk, int kc_n) {
    int mb = (int)(mr >> 7), r = (int)(mr & 127);
    int kc = kk >> 6, kl = kk & 63;
    uint32_t off = (uint32_t)(r * 128 + kl * 2);
    uint32_t sw  = off ^ ((uint32_t)(r & 7) << 4);
    return (((size_t)mb * kc_n + kc) << 13) + (sw >> 1);
}

__device__ __forceinline__ void split_store(__nv_bfloat16* hi, __nv_bfloat16* lo,
                                            size_t base, float v0, float v1) {
    __nv_bfloat16 h0 = __float2bfloat16(v0);
    __nv_bfloat16 h1 = __float2bfloat16(v1);
    *(__nv_bfloat162*)(hi + base) = __halves2bfloat162(h0, h1);
    *(__nv_bfloat162*)(lo + base) = __halves2bfloat162(
        __float2bfloat16(v0 - __bfloat162float(h0)),
        __float2bfloat16(v1 - __bfloat162float(h1)));
}

// ---------------------------------------------------------------------------
// Weight preprocessing: W (K,N) fp32 -> hi/lo bf16 (K,N) tiles (64k x 256n,
// 512B rows, 16B-chunk xor swizzle). Pure streaming convert, coalesced.
// Grid: (Npad/256, K/64), 256 threads, 8 chunks of 8 elems per thread.
// ---------------------------------------------------------------------------
__global__ void __launch_bounds__(256)
convert_b_kernel(const float* __restrict__ W,
                 __nv_bfloat16* __restrict__ Thi,
                 __nv_bfloat16* __restrict__ Tlo,
                 int K, int N)
{
    const int tid   = threadIdx.x;
    const int nbase = blockIdx.x * 256;
    const int kbase = blockIdx.y * 64;
    const size_t tile_h =
        ((size_t)blockIdx.x * (size_t)(K >> 6) + (size_t)blockIdx.y) << 14;

#pragma unroll
    for (int i = 0; i < 8; i++) {
        int id = tid + i * 256;            // 0..2047
        int k  = id >> 5;                  // 0..63
        int ch = id & 31;                  // 0..31 (8-elem chunk)
        int n  = nbase + ch * 8;
        float4 v0 = make_float4(0.f, 0.f, 0.f, 0.f);
        float4 v1 = v0;
        if (n < N) {                       // N % 8 == 0 -> chunk all-or-nothing
            const float* src = W + (size_t)(kbase + k) * N + n;
            v0 = *(const float4*)src;
            v1 = *(const float4*)(src + 4);
        }
        float vv[8] = {v0.x, v0.y, v0.z, v0.w, v1.x, v1.y, v1.z, v1.w};
        uint32_t hw[4], lw[4];
#pragma unroll
        for (int j = 0; j < 4; j++) {
            __nv_bfloat16 h0 = __float2bfloat16(vv[2 * j]);
            __nv_bfloat16 h1 = __float2bfloat16(vv[2 * j + 1]);
            __nv_bfloat162 hp = __halves2bfloat162(h0, h1);
            __nv_bfloat162 lp = __halves2bfloat162(
                __float2bfloat16(vv[2 * j]     - __bfloat162float(h0)),
                __float2bfloat16(vv[2 * j + 1] - __bfloat162float(h1)));
            hw[j] = *(uint32_t*)&hp;
            lw[j] = *(uint32_t*)&lp;
        }
        uint32_t c = ((uint32_t)ch * 16) ^ (((uint32_t)k & 7) << 4);
        size_t off_h = tile_h + ((k * 512 + c) >> 1);
        *(uint4*)(Thi + off_h) = make_uint4(hw[0], hw[1], hw[2], hw[3]);
        *(uint4*)(Tlo + off_h) = make_uint4(lw[0], lw[1], lw[2], lw[3]);
    }
}

// ---------------------------------------------------------------------------
// Activation split: A (M,K) fp32 -> hi/lo bf16 A-tiles. K = 1<<kshift.
// ---------------------------------------------------------------------------
__global__ void __launch_bounds__(256)
split_a_kernel(const float* __restrict__ A,
               __nv_bfloat16* __restrict__ hi, __nv_bfloat16* __restrict__ lo,
               int n4, int kshift)
{
    int idx = blockIdx.x * 256 + threadIdx.x;
    if (idx >= n4) return;
    const int K = 1 << kshift;
    int idx4 = idx << 2;
    size_t m = (size_t)(idx4 >> kshift);
    int k = idx4 & (K - 1);
    float4 v = ((const float4*)A)[idx];
    split_store(hi, lo, tile_off(m, k,     K >> 6), v.x, v.y);
    split_store(hi, lo, tile_off(m, k + 2, K >> 6), v.z, v.w);
}

// ---------------------------------------------------------------------------
// Split-bf16 GEMM, CTA tile 128x256, 1024 threads = 32 warps (4M x 8N),
// warp tile 32x32 (8 warps/SMSP for HMMA-pipe saturation).
// A tiles: (M,K) 128x64h (LDSM). B tiles: (K,N) 64x256 (LDSM.T).
// 2-stage bulk-copy pipeline. Split-K via blockIdx.z.
// OUT=0: C fp32 + bias/act. OUT=1: split tiles (K'=1<<ksh) + bias/act.
// OUT=2: fp32 partial at C + z*M*N (no bias/act).
// ---------------------------------------------------------------------------
#define A_TILE_B    16384
#define B_TILE_B    32768
#define STAGE_BYTES (2 * A_TILE_B + 2 * B_TILE_B)   // 98304
#define NSTAGE      2
#define TCG_SMEM    (NSTAGE * STAGE_BYTES)          // 196608

template <int ACT, int OUT>
__global__ void __launch_bounds__(1024)
tc_gemm_kernel(const __nv_bfloat16* __restrict__ Ahi,
               const __nv_bfloat16* __restrict__ Alo,
               const __nv_bfloat16* __restrict__ Bhi,
               const __nv_bfloat16* __restrict__ Blo,
               const float* __restrict__ bias, float* __restrict__ C,
               __nv_bfloat16* __restrict__ Chi, __nv_bfloat16* __restrict__ Clo,
               int ksh, int kcn_per, int M, int N, int K)
{
    extern __shared__ char dsm[];
    __shared__ uint64_t mbar[NSTAGE];

    const uint32_t sbase = smem_u32(dsm);
    uint32_t mb[NSTAGE];
#pragma unroll
    for (int i = 0; i < NSTAGE; i++) mb[i] = smem_u32(&mbar[i]);

    const int tid  = threadIdx.x;
    const int lane = tid & 31;
    const int warp = tid >> 5;
    const int wm   = warp & 3;                 // 0..3 (M dir)
    const int wn   = warp >> 2;                // 0..7 (N dir)
    const int bm   = blockIdx.y * 128;
    const int bn   = blockIdx.x * 256;
    const int g    = lane >> 2;
    const int q    = lane & 3;

    // A fragment addressing (128x64h tile, non-trans LDSM)
    const int ar = lane & 15;
    const int ac = (lane >> 4) * 16;
    const uint32_t a_xor = (uint32_t)(ar & 7) << 4;
    uint32_t a_row_off[2];
#pragma unroll
    for (int mi = 0; mi < 2; mi++)
        a_row_off[mi] = (uint32_t)((wm * 32 + mi * 16 + ar) * 128);

    // B fragment addressing (64x256 tile, 512B rows, LDSM.T)
    const int bk  = (lane & 7) + (((lane >> 3) & 1) << 3);   // 0..15
    const int bno = (lane >> 4) << 3;                        // 0 or 8
    const uint32_t b_xor = ((uint32_t)bk & 7) << 4;
    const uint32_t bkb   = (uint32_t)bk * 512;
    uint32_t b_cn[2];
#pragma unroll
    for (int nj = 0; nj < 2; nj++)
        b_cn[nj] = ((uint32_t)((wn * 32 + nj * 16 + bno) * 2)) ^ b_xor;

    if (tid == 0)
#pragma unroll
        for (int i = 0; i < NSTAGE; i++) MBARRIER_INIT(mb[i], 1);
    __syncthreads();

    const int kcn = K >> 6;
    const int koff = blockIdx.z * kcn_per;
    const size_t a_tile0 = (size_t)blockIdx.y * kcn + koff;
    const size_t b_tile0 = (size_t)blockIdx.x * kcn + koff;

    auto fill = [&](int c, int s) {            // tid 0 only
        MBARRIER_EXPECT_TX(mb[s], STAGE_BYTES);
        const uint32_t st = sbase + s * STAGE_BYTES;
        const size_t ao = (a_tile0 + c) << 13;
        const size_t bo = (b_tile0 + c) << 14;
        bulk_g2s(st,                Ahi + ao, A_TILE_B, mb[s]);
        bulk_g2s(st + A_TILE_B,     Alo + ao, A_TILE_B, mb[s]);
        bulk_g2s(st + 2 * A_TILE_B, Bhi + bo, B_TILE_B, mb[s]);
        bulk_g2s(st + 2 * A_TILE_B + B_TILE_B, Blo + bo, B_TILE_B, mb[s]);
    };

    float acc[2][4][4];
#pragma unroll
    for (int mi = 0; mi < 2; mi++)
#pragma unroll
        for (int ni = 0; ni < 4; ni++)
#pragma unroll
            for (int f = 0; f < 4; f++) acc[mi][ni][f] = 0.f;

    if (tid == 0)
        for (int c = 0; c < NSTAGE && c < kcn_per; c++) fill(c, c);

    int ph[NSTAGE] = {0, 0};
    int s = 0;
    for (int c = 0; c < kcn_per; c++) {
        MBARRIER_WAIT_PARITY(mb[s], ph[s]);
        ph[s] ^= 1;

        const uint32_t st = sbase + s * STAGE_BYTES;
        const uint32_t Ah = st;
        const uint32_t Al = st + A_TILE_B;
        const uint32_t Bh = st + 2 * A_TILE_B;
        const uint32_t Bl = Bh + B_TILE_B;

#pragma unroll
        for (int ks = 0; ks < 4; ks++) {
            const uint32_t bko = bkb + (uint32_t)ks * 8192;   // 16 k-rows
            const uint32_t ako = (uint32_t)(ks * 32 + ac);
#pragma unroll
            for (int nj = 0; nj < 2; nj++) {
                uint32_t bh[4], bl[4];
                uint32_t boff = bko + b_cn[nj];
                LDSM4T(bh, Bh + boff);
                LDSM4T(bl, Bl + boff);
#pragma unroll
                for (int mi = 0; mi < 2; mi++) {
                    uint32_t ah[4], al[4];
                    uint32_t aoff = a_row_off[mi] + (ako ^ a_xor);
                    LDSM4(ah, Ah + aoff);
                    LDSM4(al, Al + aoff);
#pragma unroll
                    for (int hf = 0; hf < 2; hf++) {
                        float* ap = acc[mi][nj * 2 + hf];
                        MMA_BF16(ap, ah[0], ah[1], ah[2], ah[3],
                                 bh[hf * 2], bh[hf * 2 + 1]);
                        MMA_BF16(ap, ah[0], ah[1], ah[2], ah[3],
                                 bl[hf * 2], bl[hf * 2 + 1]);
                        MMA_BF16(ap, al[0], al[1], al[2], al[3],
                                 bh[hf * 2], bh[hf * 2 + 1]);
                    }
                }
            }
        }
        __syncthreads();                        // all reads of stage s done
        if (tid == 0 && c + NSTAGE < kcn_per) fill(c + NSTAGE, s);
        s ^= 1;
    }

    // ---- epilogue (N even everywhere -> pairwise guard ok)
    const int Kc = 1 << ksh;
    float* Cp = (OUT == 2) ? (C + (size_t)blockIdx.z * M * N) : C;
#pragma unroll
    for (int mi = 0; mi < 2; mi++) {
        const int m0 = bm + wm * 32 + mi * 16;
#pragma unroll
        for (int ni = 0; ni < 4; ni++) {
            const int n = bn + wn * 32 + ni * 8 + 2 * q;
            if (n >= N) continue;
            float b0 = 0.f, b1 = 0.f;
            if (OUT != 2 && bias) { b0 = bias[n]; b1 = bias[n + 1]; }
#pragma unroll
            for (int hf = 0; hf < 2; hf++) {
                const int m = m0 + g + hf * 8;
                float v0 = acc[mi][ni][hf * 2 + 0] + b0;
                float v1 = acc[mi][ni][hf * 2 + 1] + b1;
                if (OUT != 2 && ACT == 1) {
                    v0 = fmaxf(v0, 0.f); v1 = fmaxf(v1, 0.f);
                }
                if (OUT == 1) {
                    size_t flat = (size_t)m * N + n;
                    size_t mr = flat >> ksh;
                    int kk = (int)(flat & (Kc - 1));
                    split_store(Chi, Clo, tile_off(mr, kk, Kc >> 6), v0, v1);
                } else {
                    *(float2*)(Cp + (size_t)m * N + n) = make_float2(v0, v1);
                }
            }
        }
    }

    __syncthreads();
    if (tid == 0)
#pragma unroll
        for (int i = 0; i < NSTAGE; i++) MBARRIER_INVAL(mb[i]);
}

// ---------------------------------------------------------------------------
// Split-K reduce: sum nsplit partials, add bias, act; OUT=0 fp32, OUT=1 tiles.
// ---------------------------------------------------------------------------
template <int ACT, int OUT>
__global__ void __launch_bounds__(256)
reduce_kernel(const float* __restrict__ P, int nsplit, size_t MN,
              const float* __restrict__ bias, int nmask,
              float* __restrict__ C,
              __nv_bfloat16* __restrict__ Chi, __nv_bfloat16* __restrict__ Clo,
              int ksh)
{
    size_t f = ((size_t)blockIdx.x * 256 + threadIdx.x) * 2;
    if (f >= MN) return;
    float v0 = 0.f, v1 = 0.f;
#pragma unroll 4
    for (int z = 0; z < nsplit; z++) {
        float2 p = *(const float2*)(P + (size_t)z * MN + f);
        v0 += p.x; v1 += p.y;
    }
    if (bias) {
        int n = (int)(f & nmask);
        v0 += bias[n]; v1 += bias[n + 1];
    }
    if (ACT == 1) { v0 = fmaxf(v0, 0.f); v1 = fmaxf(v1, 0.f); }
    if (OUT == 0) {
        *(float2*)(C + f) = make_float2(v0, v1);
    } else {
        size_t mr = f >> ksh;
        int kk = (int)(f & ((1 << ksh) - 1));
        split_store(Chi, Clo, tile_off(mr, kk, (1 << ksh) >> 6), v0, v1);
    }
}

// ---------------------------------------------------------------------------
// Fused conv+SiLU+dt+scan. One CTA per (batch, head), 256 threads.
// ---------------------------------------------------------------------------
__global__ void __launch_bounds__(256)
fused_scan_kernel(const float* __restrict__ zx,
                  const float* __restrict__ conv_w,
                  const float* __restrict__ conv_b,
                  const float* __restrict__ dt_bias,
                  const float* __restrict__ A_log,
                  const float* __restrict__ Dp,
                  float* __restrict__ y)
{
    const int b = blockIdx.x;
    const int h = blockIdx.y;
    const int t = threadIdx.x;

    __shared__ float Bsh[SEQL][DSTATE];
    __shared__ float Csh[SEQL][DSTATE];
    __shared__ float xsh[SEQL][HEADDIM];
    __shared__ float dts[SEQL], dAs[SEQL];

    const float* zrow = zx + (size_t)b * SEQL * DPROJ;

    {
        const int ch  = 2048 + t;
        const int src = D_INNER + ch;
        const float w0 = conv_w[ch * 4 + 0], w1 = conv_w[ch * 4 + 1];
        const float w2 = conv_w[ch * 4 + 2], w3 = conv_w[ch * 4 + 3];
        const float bb = conv_b[ch];
        float v[SEQL];
#pragma unroll
        for (int l = 0; l < SEQL; l++) v[l] = zrow[(size_t)l * DPROJ + src];
#pragma unroll
        for (int l = 0; l < SEQL; l++) {
            float sv = bb + v[l] * w3;
            if (l >= 1) sv += v[l - 1] * w2;
            if (l >= 2) sv += v[l - 2] * w1;
            if (l >= 3) sv += v[l - 3] * w0;
            sv = sv / (1.f + expf(-sv));
            if (t < 128) Bsh[l][t] = sv;
            else         Csh[l][t - 128] = sv;
        }
    }
    if (t < HEADDIM) {
        const int ch  = h * HEADDIM + t;
        const int src = D_INNER + ch;
        const float w0 = conv_w[ch * 4 + 0], w1 = conv_w[ch * 4 + 1];
        const float w2 = conv_w[ch * 4 + 2], w3 = conv_w[ch * 4 + 3];
        const float bb = conv_b[ch];
        float v[SEQL];
#pragma unroll
        for (int l = 0; l < SEQL; l++) v[l] = zrow[(size_t)l * DPROJ + src];
#pragma unroll
        for (int l = 0; l < SEQL; l++) {
            float sv = bb + v[l] * w3;
            if (l >= 1) sv += v[l - 1] * w2;
            if (l >= 2) sv += v[l - 2] * w1;
            if (l >= 3) sv += v[l - 3] * w0;
            xsh[l][t] = sv / (1.f + expf(-sv));
        }
    }
    if (t >= 64 && t < 64 + SEQL) {
        const int l = t - 64;
        float xr = zrow[(size_t)l * DPROJ + (D_INNER + CONV_DIM) + h] + dt_bias[h];
        float dt = (xr > 20.f) ? xr : log1pf(expf(xr));
        dts[l] = dt;
        dAs[l] = expf(-expf(A_log[h]) * dt);
    }
    __syncthreads();

    const int p = t >> 2;
    const int q = t & 3;
    float st[32];
#pragma unroll
    for (int i = 0; i < 32; i++) st[i] = 0.f;
    const float Dh = Dp[h];

#pragma unroll
    for (int l = 0; l < SEQL; l++) {
        const float xv   = xsh[l][p];
        const float coef = dts[l] * xv;
        const float dAv  = dAs[l];
        float part = 0.f;
#pragma unroll
        for (int i = 0; i < 32; i++) {
            const int sidx = q + 4 * i;
            st[i] = fmaf(dAv, st[i], coef * Bsh[l][sidx]);
            part  = fmaf(st[i], Csh[l][sidx], part);
        }
        part += __shfl_down_sync(0xffffffffu, part, 2);
        part += __shfl_down_sync(0xffffffffu, part, 1);
        if (q == 0)
            y[((size_t)b * SEQL + l) * D_INNER + h * HEADDIM + p] = part + xv * Dh;
    }
}

// ---------------------------------------------------------------------------
// y = y * silu(z); y *= rsqrt(mean(y^2)+1e-5) * norm_w; emit split A-tiles.
// ---------------------------------------------------------------------------
__global__ void __launch_bounds__(256)
gated_rmsnorm_split_kernel(const float* __restrict__ ybuf,
                           const float* __restrict__ zx,
                           const float* __restrict__ norm_w,
                           __nv_bfloat16* __restrict__ hi,
                           __nv_bfloat16* __restrict__ lo)
{
    const size_t row = blockIdx.x;
    const int t = threadIdx.x;
    const int d0 = t * 8;
    const float* yb = ybuf + row * D_INNER;
    const float* zb = zx   + row * DPROJ;

    float v[8];
    float ss = 0.f;
#pragma unroll
    for (int j = 0; j < 8; j += 4) {
        float4 yv = *(const float4*)(yb + d0 + j);
        float4 zv = *(const float4*)(zb + d0 + j);
        v[j + 0] = yv.x * (zv.x / (1.f + expf(-zv.x)));
        v[j + 1] = yv.y * (zv.y / (1.f + expf(-zv.y)));
        v[j + 2] = yv.z * (zv.z / (1.f + expf(-zv.z)));
        v[j + 3] = yv.w * (zv.w / (1.f + expf(-zv.w)));
        ss = fmaf(v[j+0], v[j+0], ss); ss = fmaf(v[j+1], v[j+1], ss);
        ss = fmaf(v[j+2], v[j+2], ss); ss = fmaf(v[j+3], v[j+3], ss);
    }
#pragma unroll
    for (int o = 16; o > 0; o >>= 1)
        ss += __shfl_down_sync(0xffffffffu, ss, o);

    __shared__ float red[8];
    __shared__ float s_scale;
    if ((t & 31) == 0) red[t >> 5] = ss;
    __syncthreads();
    if (t == 0) {
        float s = 0.f;
        for (int i = 0; i < 8; i++) s += red[i];
        s_scale = rsqrtf(s / (float)D_INNER + 1e-5f);
    }
    __syncthreads();
    const float scale = s_scale;

#pragma unroll
    for (int j = 0; j < 8; j += 2) {
        int d = d0 + j;
        float v0 = v[j]     * scale * norm_w[d];
        float v1 = v[j + 1] * scale * norm_w[d + 1];
        split_store(hi, lo, tile_off(row, d, D_INNER >> 6), v0, v1);
    }
}

// ---------------------------------------------------------------------------
// Final tiny layer: out = A(256x1024) @ W(1024x2) + b. One CTA per row.
// ---------------------------------------------------------------------------
__global__ void __launch_bounds__(256)
final_kernel(const float* __restrict__ A, const float* __restrict__ W,
             const float* __restrict__ bias, float* __restrict__ out)
{
    const int m = blockIdx.x;
    const int t = threadIdx.x;
    float4 a = ((const float4*)(A + (size_t)m * 1024))[t];
    const float4 w0 = ((const float4*)W)[2 * t];
    const float4 w1 = ((const float4*)W)[2 * t + 1];
    float s0 = a.x * w0.x + a.y * w0.z + a.z * w1.x + a.w * w1.z;
    float s1 = a.x * w0.y + a.y * w0.w + a.z * w1.y + a.w * w1.w;
#pragma unroll
    for (int o = 16; o > 0; o >>= 1) {
        s0 += __shfl_down_sync(0xffffffffu, s0, o);
        s1 += __shfl_down_sync(0xffffffffu, s1, o);
    }
    __shared__ float r0[8], r1[8];
    if ((t & 31) == 0) { r0[t >> 5] = s0; r1[t >> 5] = s1; }
    __syncthreads();
    if (t == 0) {
        float a0 = 0.f, a1 = 0.f;
        for (int i = 0; i < 8; i++) { a0 += r0[i]; a1 += r1[i]; }
        out[m * 2 + 0] = a0 + bias[0];
        out[m * 2 + 1] = a1 + bias[1];
    }
}

// ---------------------------------------------------------------------------
// Host-side orchestration
// ---------------------------------------------------------------------------
struct MambaW {
    const float *in_proj, *conv_w, *conv_b, *dt_bias, *A_log, *D, *norm_w, *out_proj;
};

extern "C" void kernel_launch(void* const* d_in, const int* in_sizes, int n_in,
                              void* d_out, int out_size)
{
    const float* x      = (const float*)d_in[0];
    const float* w_in1  = (const float*)d_in[1];
    const float* b_in1  = (const float*)d_in[2];
    const float* w_in2  = (const float*)d_in[3];
    const float* b_in2  = (const float*)d_in[4];
    MambaW m1 = { (const float*)d_in[5],  (const float*)d_in[6],  (const float*)d_in[7],
                  (const float*)d_in[8],  (const float*)d_in[9],  (const float*)d_in[10],
                  (const float*)d_in[11], (const float*)d_in[12] };
    MambaW m2 = { (const float*)d_in[13], (const float*)d_in[14], (const float*)d_in[15],
                  (const float*)d_in[16], (const float*)d_in[17], (const float*)d_in[18],
                  (const float*)d_in[19], (const float*)d_in[20] };
    const float* w_out1 = (const float*)d_in[21];
    const float* b_out1 = (const float*)d_in[22];
    const float* w_out2 = (const float*)d_in[23];
    const float* b_out2 = (const float*)d_in[24];
    float* out = (float*)d_out;

    cudaFuncSetAttribute(tc_gemm_kernel<0, 0>,
                         cudaFuncAttributeMaxDynamicSharedMemorySize, TCG_SMEM);
    cudaFuncSetAttribute(tc_gemm_kernel<0, 1>,
                         cudaFuncAttributeMaxDynamicSharedMemorySize, TCG_SMEM);
    cudaFuncSetAttribute(tc_gemm_kernel<0, 2>,
                         cudaFuncAttributeMaxDynamicSharedMemorySize, TCG_SMEM);
    cudaFuncSetAttribute(tc_gemm_kernel<1, 0>,
                         cudaFuncAttributeMaxDynamicSharedMemorySize, TCG_SMEM);

    float *a, *zx, *ybuf, *part;
    __nv_bfloat16 *whi, *wlo, *p1h, *p1l, *p2h, *p2l;
    cudaGetSymbolAddress((void**)&a,    g_a);
    cudaGetSymbolAddress((void**)&zx,   g_zx);
    cudaGetSymbolAddress((void**)&ybuf, g_y);
    cudaGetSymbolAddress((void**)&part, g_part);
    cudaGetSymbolAddress((void**)&whi,  g_whi);
    cudaGetSymbolAddress((void**)&wlo,  g_wlo);
    cudaGetSymbolAddress((void**)&p1h,  g_p1hi);
    cudaGetSymbolAddress((void**)&p1l,  g_p1lo);
    cudaGetSymbolAddress((void**)&p2h,  g_p2hi);
    cudaGetSymbolAddress((void**)&p2l,  g_p2lo);

    // ---- weight preprocessing (streaming convert, no transpose)
    auto cvt = [&](const float* W, size_t off, int K, int N, int Npad) {
        convert_b_kernel<<<dim3(Npad / 256, K / 64), 256>>>(
            W, whi + off, wlo + off, K, N);
    };
    cvt(w_in1,       OFF_WIN1,    1024, 8192, 8192);
    cvt(w_in2,       OFF_WIN2,    8192, 8192, 8192);
    cvt(m1.in_proj,  OFF_M1_INP,  1024, DPROJ, 4608);
    cvt(m2.in_proj,  OFF_M2_INP,  1024, DPROJ, 4608);
    cvt(m1.out_proj, OFF_M1_OUTP, 2048, 1024, 1024);
    cvt(m2.out_proj, OFF_M2_OUTP, 2048, 1024, 1024);
    cvt(w_out1,      OFF_WOUT1,   8192, 1024, 1024);

    // ---- split x -> p1 (256 x 1024, kshift 10)
    split_a_kernel<<<(BATCH * 1024 / 4 + 255) / 256, 256>>>(x, p1h, p1l,
                                                            BATCH * 1024 / 4, 10);

    const size_t MN_256x8192  = (size_t)BATCH * 8192;
    const size_t MN_2048x1024 = (size_t)ROWS * 1024;
    const size_t MN_256x1024  = (size_t)BATCH * 1024;

    // ---- MLP in (split-K x4)
    tc_gemm_kernel<0, 2><<<dim3(32, 2, 4), 1024, TCG_SMEM>>>(
        p1h, p1l, whi + OFF_WIN1, wlo + OFF_WIN1, nullptr,
        part, nullptr, nullptr, 13, 4, BATCH, 8192, 1024);
    reduce_kernel<1, 1><<<(unsigned)(MN_256x8192 / 512), 256>>>(
        part, 4, MN_256x8192, b_in1, 8191, nullptr, p2h, p2l, 13);
    tc_gemm_kernel<0, 2><<<dim3(32, 2, 4), 1024, TCG_SMEM>>>(
        p2h, p2l, whi + OFF_WIN2, wlo + OFF_WIN2, nullptr,
        part, nullptr, nullptr, 10, 32, BATCH, 8192, 8192);
    reduce_kernel<0, 1><<<(unsigned)(MN_256x8192 / 512), 256>>>(
        part, 4, MN_256x8192, b_in2, 8191, nullptr, p1h, p1l, 10);

    // ---- 2x Mamba2 layers (h tiles live in p1 as (2048, 1024))
    const MambaW* layers[2] = { &m1, &m2 };
    const size_t inp_off[2]  = { OFF_M1_INP,  OFF_M2_INP };
    const size_t outp_off[2] = { OFF_M1_OUTP, OFF_M2_OUTP };
    for (int li = 0; li < 2; li++) {
        const MambaW& p = *layers[li];
        // zx = h @ in_proj (fp32 out, 288 CTAs, no split)
        tc_gemm_kernel<0, 0><<<dim3(18, 16, 1), 1024, TCG_SMEM>>>(
            p1h, p1l, whi + inp_off[li], wlo + inp_off[li], nullptr,
            zx, nullptr, nullptr, 0, 16, ROWS, DPROJ, 1024);
        fused_scan_kernel<<<dim3(BATCH, NHEADS), 256>>>(
            zx, p.conv_w, p.conv_b, p.dt_bias, p.A_log, p.D, ybuf);
        gated_rmsnorm_split_kernel<<<ROWS, 256>>>(ybuf, zx, p.norm_w, p2h, p2l);
        // h = y @ out_proj: split-K x4, reduce -> p1 tiles
        int ksh_next = (li == 0) ? 10 : 13;
        tc_gemm_kernel<0, 2><<<dim3(4, 16, 4), 1024, TCG_SMEM>>>(
            p2h, p2l, whi + outp_off[li], wlo + outp_off[li], nullptr,
            part, nullptr, nullptr, ksh_next, 8, ROWS, 1024, 2048);
        reduce_kernel<0, 1><<<(unsigned)(MN_2048x1024 / 512), 256>>>(
            part, 4, MN_2048x1024, nullptr, 1023, nullptr, p1h, p1l, ksh_next);
    }

    // ---- MLP out: split-K x32, reduce(relu+bias) -> fp32 a; final dot
    tc_gemm_kernel<0, 2><<<dim3(4, 2, 32), 1024, TCG_SMEM>>>(
        p1h, p1l, whi + OFF_WOUT1, wlo + OFF_WOUT1, nullptr,
        part, nullptr, nullptr, 0, 4, BATCH, 1024, 8192);
    reduce_kernel<1, 0><<<(unsigned)(MN_256x1024 / 512), 256>>>(
        part, 32, MN_256x1024, b_out1, 1023, a, nullptr, nullptr, 0);
    final_kernel<<<BATCH, 256>>>(a, w_out2, b_out2, out);
}

// round 14
// speedup vs baseline: 1.1156x; 1.0548x over previous
#include <cuda_runtime.h>
#include <cuda_bf16.h>
#include <cstdint>

// ---------------------------------------------------------------------------
// Problem dimensions (fixed by the reference)
// ---------------------------------------------------------------------------
#define BATCH    256
#define SEQL     8
#define HIDD     1024            // HID
#define D_INNER  2048
#define DSTATE   128
#define NHEADS   32
#define HEADDIM  64
#define CONV_DIM 2304            // D_INNER + 2*DSTATE
#define DPROJ    4384            // 2*D_INNER + 2*DSTATE + NHEADS
#define ROWS     (BATCH * SEQL)  // 2048

// ---------------------------------------------------------------------------
// Scratch (static device buffers; no allocation allowed in kernel_launch)
// ---------------------------------------------------------------------------
__device__ float g_a   [BATCH * 8192];    // fp32 intermediate (out1 output)
__device__ float g_zx  [ROWS  * DPROJ];   // zxbcdt (2048 x 4384)
__device__ float g_y   [ROWS  * D_INNER]; // SSM output (2048 x 2048)
__device__ float g_part[8388608];         // split-K partials

// Two ping-pong split-bf16 tiled activation buffers (max 2048x2048)
#define AMAX 4194304
__device__ __nv_bfloat16 g_p1hi[AMAX];
__device__ __nv_bfloat16 g_p1lo[AMAX];
__device__ __nv_bfloat16 g_p2hi[AMAX];
__device__ __nv_bfloat16 g_p2lo[AMAX];

// Split-bf16 tiled weights. B tile = 64 k-rows x 256 n-cols, (K,N) layout,
// 512B per k-row, 16B chunks xor-swizzled by (k&7)<<4. One tile = 32KB
// contiguous; tile index = nb * (K/64) + kc. N padded to mult of 256.
#define OFF_WIN1     0ULL
#define OFF_WIN2     8388608ULL      // win1: 8192*1024
#define OFF_M1_INP   75497472ULL     // win2: 8192*8192
#define OFF_M2_INP   80216064ULL     // inproj: 4608*1024
#define OFF_M1_OUTP  84934656ULL
#define OFF_M2_OUTP  87031808ULL     // outproj: 1024*2048
#define OFF_WOUT1    89128960ULL
#define WT_TOTAL     97517568ULL     // + wout1: 1024*8192
__device__ __nv_bfloat16 g_whi[WT_TOTAL];
__device__ __nv_bfloat16 g_wlo[WT_TOTAL];

// ---------------------------------------------------------------------------
// PTX helpers
// ---------------------------------------------------------------------------
__device__ __forceinline__ uint32_t smem_u32(const void* p) {
    uint32_t a;
    asm("{ .reg .u64 t; cvta.to.shared.u64 t, %1; cvt.u32.u64 %0, t; }"
        : "=r"(a) : "l"(p));
    return a;
}

#define MBARRIER_INIT(addr, count) \
    asm volatile("mbarrier.init.shared.b64 [%0], %1;" \
                 :: "r"((uint32_t)(addr)), "r"((uint32_t)(count)) : "memory")
#define MBARRIER_INVAL(addr) \
    asm volatile("mbarrier.inval.shared.b64 [%0];" \
                 :: "r"((uint32_t)(addr)) : "memory")
#define MBARRIER_EXPECT_TX(addr, bytes) \
    asm volatile("mbarrier.arrive.expect_tx.shared.b64 _, [%0], %1;" \
                 :: "r"((uint32_t)(addr)), "r"((uint32_t)(bytes)) : "memory")
#define MBARRIER_ARRIVE(addr) \
    asm volatile("mbarrier.arrive.shared.b64 _, [%0];" \
                 :: "r"((uint32_t)(addr)) : "memory")

#define MBARRIER_WAIT_PARITY(addr, par) do {                                   \
    uint32_t _m = (uint32_t)(addr), _p = (uint32_t)(par), _d;                  \
    asm volatile(                                                              \
        "{\n\t.reg .pred p;\n\t"                                               \
        "mbarrier.try_wait.parity.acquire.cta.shared::cta.b64 p, [%1], %2;\n\t"\
        "selp.b32 %0, 1, 0, p;\n\t}"                                           \
        : "=r"(_d) : "r"(_m), "r"(_p) : "memory");                             \
    if (!_d) {                                                                 \
        asm volatile(                                                          \
            "{\n\t.reg .pred P1;\n\t"                                          \
            "WL_%=:\n\t"                                                       \
            "mbarrier.try_wait.parity.acquire.cta.shared::cta.b64 P1, [%0], %1, 0x989680;\n\t" \
            "@P1 bra.uni WD_%=;\n\t"                                           \
            "bra.uni WL_%=;\n\t"                                               \
            "WD_%=:\n\t}"                                                      \
            :: "r"(_m), "r"(_p) : "memory");                                   \
    }                                                                          \
} while (0)

__device__ __forceinline__ void bulk_g2s(uint32_t sdst, const void* gsrc,
                                         uint32_t bytes, uint32_t mbar) {
    asm volatile(
        "cp.async.bulk.shared::cluster.global.mbarrier::complete_tx::bytes "
        "[%0], [%1], %2, [%3];"
        :: "r"(sdst), "l"(gsrc), "r"(bytes), "r"(mbar) : "memory");
}

#define LDSM4(r, addr) \
    asm volatile("ldmatrix.sync.aligned.m8n8.x4.shared.b16 {%0,%1,%2,%3}, [%4];" \
                 : "=r"((r)[0]), "=r"((r)[1]), "=r"((r)[2]), "=r"((r)[3]) \
                 : "r"(addr))

#define LDSM4T(r, addr) \
    asm volatile("ldmatrix.sync.aligned.m8n8.x4.trans.shared.b16 {%0,%1,%2,%3}, [%4];" \
                 : "=r"((r)[0]), "=r"((r)[1]), "=r"((r)[2]), "=r"((r)[3]) \
                 : "r"(addr))

#define MMA_BF16(ACCP, A0, A1, A2, A3, B0, B1)                              \
    asm volatile(                                                           \
        "mma.sync.aligned.m16n8k16.row.col.f32.bf16.bf16.f32 "              \
        "{%0,%1,%2,%3}, {%4,%5,%6,%7}, {%8,%9}, {%0,%1,%2,%3};\n"           \
        : "+f"((ACCP)[0]), "+f"((ACCP)[1]), "+f"((ACCP)[2]), "+f"((ACCP)[3])\
        : "r"(A0), "r"(A1), "r"(A2), "r"(A3), "r"(B0), "r"(B1))

// A-side split-tile address: element (row mr, col kk) of an (M,Kc) operand in
// 128x64 swizzled tiles; returns offset in halves. kk must be even.
__device__ __forceinline__ size_t tile_off(size_t mr, int kk, int kc_n) {
    int mb = (int)(mr >> 7), r = (int)(mr & 127);
    int kc = kk >> 6, kl = kk & 63;
    uint32_t off = (uint32_t)(r * 128 + kl * 2);
    uint32_t sw  = off ^ ((uint32_t)(r & 7) << 4);
    return (((size_t)mb * kc_n + kc) << 13) + (sw >> 1);
}

__device__ __forceinline__ void split_store(__nv_bfloat16* hi, __nv_bfloat16* lo,
                                            size_t base, float v0, float v1) {
    __nv_bfloat16 h0 = __float2bfloat16(v0);
    __nv_bfloat16 h1 = __float2bfloat16(v1);
    *(__nv_bfloat162*)(hi + base) = __halves2bfloat162(h0, h1);
    *(__nv_bfloat162*)(lo + base) = __halves2bfloat162(
        __float2bfloat16(v0 - __bfloat162float(h0)),
        __float2bfloat16(v1 - __bfloat162float(h1)));
}

// ---------------------------------------------------------------------------
// Weight preprocessing: W (K,N) fp32 -> hi/lo bf16 (K,N) tiles (64k x 256n,
// 512B rows, 16B-chunk xor swizzle). Pure streaming convert, coalesced.
// All 8 load pairs issued up-front (MLP=8) before any convert/store.
// Grid: (Npad/256, K/64), 256 threads.
// ---------------------------------------------------------------------------
__global__ void __launch_bounds__(256)
convert_b_kernel(const float* __restrict__ W,
                 __nv_bfloat16* __restrict__ Thi,
                 __nv_bfloat16* __restrict__ Tlo,
                 int K, int N)
{
    const int tid   = threadIdx.x;
    const int nbase = blockIdx.x * 256;
    const int kbase = blockIdx.y * 64;
    const size_t tile_h =
        ((size_t)blockIdx.x * (size_t)(K >> 6) + (size_t)blockIdx.y) << 14;

    float4 va[8], vb[8];
#pragma unroll
    for (int i = 0; i < 8; i++) {
        int id = tid + i * 256;            // 0..2047
        int k  = id >> 5;                  // 0..63
        int ch = id & 31;                  // 0..31 (8-elem chunk)
        int n  = nbase + ch * 8;
        va[i] = make_float4(0.f, 0.f, 0.f, 0.f);
        vb[i] = va[i];
        if (n < N) {                       // N % 8 == 0 -> chunk all-or-nothing
            const float* src = W + (size_t)(kbase + k) * N + n;
            va[i] = *(const float4*)src;
            vb[i] = *(const float4*)(src + 4);
        }
    }

#pragma unroll
    for (int i = 0; i < 8; i++) {
        int id = tid + i * 256;
        int k  = id >> 5;
        int ch = id & 31;
        float vv[8] = {va[i].x, va[i].y, va[i].z, va[i].w,
                       vb[i].x, vb[i].y, vb[i].z, vb[i].w};
        uint32_t hw[4], lw[4];
#pragma unroll
        for (int j = 0; j < 4; j++) {
            __nv_bfloat16 h0 = __float2bfloat16(vv[2 * j]);
            __nv_bfloat16 h1 = __float2bfloat16(vv[2 * j + 1]);
            __nv_bfloat162 hp = __halves2bfloat162(h0, h1);
            __nv_bfloat162 lp = __halves2bfloat162(
                __float2bfloat16(vv[2 * j]     - __bfloat162float(h0)),
                __float2bfloat16(vv[2 * j + 1] - __bfloat162float(h1)));
            hw[j] = *(uint32_t*)&hp;
            lw[j] = *(uint32_t*)&lp;
        }
        uint32_t c = ((uint32_t)ch * 16) ^ (((uint32_t)k & 7) << 4);
        size_t off_h = tile_h + ((k * 512 + c) >> 1);
        *(uint4*)(Thi + off_h) = make_uint4(hw[0], hw[1], hw[2], hw[3]);
        *(uint4*)(Tlo + off_h) = make_uint4(lw[0], lw[1], lw[2], lw[3]);
    }
}

// ---------------------------------------------------------------------------
// Activation split: A (M,K) fp32 -> hi/lo bf16 A-tiles. K = 1<<kshift.
// ---------------------------------------------------------------------------
__global__ void __launch_bounds__(256)
split_a_kernel(const float* __restrict__ A,
               __nv_bfloat16* __restrict__ hi, __nv_bfloat16* __restrict__ lo,
               int n4, int kshift)
{
    int idx = blockIdx.x * 256 + threadIdx.x;
    if (idx >= n4) return;
    const int K = 1 << kshift;
    int idx4 = idx << 2;
    size_t m = (size_t)(idx4 >> kshift);
    int k = idx4 & (K - 1);
    float4 v = ((const float4*)A)[idx];
    split_store(hi, lo, tile_off(m, k,     K >> 6), v.x, v.y);
    split_store(hi, lo, tile_off(m, k + 2, K >> 6), v.z, v.w);
}

// ---------------------------------------------------------------------------
// Split-bf16 GEMM, CTA tile 128x256, 512 threads (16 warps 4Mx4N, warp 32x64).
// A tiles: (M,K) 128x64h (LDSM). B tiles: (K,N) 64x256 (LDSM.T).
// 2-stage bulk-copy pipeline with full/empty mbarrier pairs (no per-slab
// __syncthreads): lane-0 of each warp arrives on empty[s] after its last
// read of stage s; tid0 issues the next fill as soon as empty[s] completes.
// Split-K via blockIdx.z.
// OUT=0: C fp32 + bias/act. OUT=1: split tiles (K'=1<<ksh) + bias/act.
// OUT=2: fp32 partial at C + z*M*N (no bias/act).
// ---------------------------------------------------------------------------
#define A_TILE_B    16384
#define B_TILE_B    32768
#define STAGE_BYTES (2 * A_TILE_B + 2 * B_TILE_B)   // 98304
#define NSTAGE      2
#define TCG_SMEM    (NSTAGE * STAGE_BYTES)          // 196608

template <int ACT, int OUT>
__global__ void __launch_bounds__(512)
tc_gemm_kernel(const __nv_bfloat16* __restrict__ Ahi,
               const __nv_bfloat16* __restrict__ Alo,
               const __nv_bfloat16* __restrict__ Bhi,
               const __nv_bfloat16* __restrict__ Blo,
               const float* __restrict__ bias, float* __restrict__ C,
               __nv_bfloat16* __restrict__ Chi, __nv_bfloat16* __restrict__ Clo,
               int ksh, int kcn_per, int M, int N, int K)
{
    extern __shared__ char dsm[];
    __shared__ uint64_t mbar_f[NSTAGE];    // full  (tx-count)
    __shared__ uint64_t mbar_e[NSTAGE];    // empty (16 warp arrivals)

    const uint32_t sbase = smem_u32(dsm);
    uint32_t mbf[NSTAGE], mbe[NSTAGE];
#pragma unroll
    for (int i = 0; i < NSTAGE; i++) {
        mbf[i] = smem_u32(&mbar_f[i]);
        mbe[i] = smem_u32(&mbar_e[i]);
    }

    const int tid  = threadIdx.x;
    const int lane = tid & 31;
    const int warp = tid >> 5;
    const int wm   = warp >> 2;                // 0..3 (M dir)
    const int wn   = warp & 3;                 // 0..3 (N dir)
    const int bm   = blockIdx.y * 128;
    const int bn   = blockIdx.x * 256;
    const int g    = lane >> 2;
    const int q    = lane & 3;

    // A fragment addressing (128x64h tile, non-trans LDSM)
    const int ar = lane & 15;
    const int ac = (lane >> 4) * 16;
    const uint32_t a_xor = (uint32_t)(ar & 7) << 4;
    uint32_t a_row_off[2];
#pragma unroll
    for (int mi = 0; mi < 2; mi++)
        a_row_off[mi] = (uint32_t)((wm * 32 + mi * 16 + ar) * 128);

    // B fragment addressing (64x256 tile, 512B rows, LDSM.T)
    const int bk  = (lane & 7) + (((lane >> 3) & 1) << 3);   // 0..15
    const int bno = (lane >> 4) << 3;                        // 0 or 8
    const uint32_t b_xor = ((uint32_t)bk & 7) << 4;
    const uint32_t bkb   = (uint32_t)bk * 512;
    uint32_t b_cn[4];
#pragma unroll
    for (int nj = 0; nj < 4; nj++)
        b_cn[nj] = ((uint32_t)((wn * 64 + nj * 16 + bno) * 2)) ^ b_xor;

    if (tid == 0)
#pragma unroll
        for (int i = 0; i < NSTAGE; i++) {
            MBARRIER_INIT(mbf[i], 1);
            MBARRIER_INIT(mbe[i], 16);         // one arrive per warp
        }
    __syncthreads();

    const int kcn = K >> 6;
    const int koff = blockIdx.z * kcn_per;
    const size_t a_tile0 = (size_t)blockIdx.y * kcn + koff;
    const size_t b_tile0 = (size_t)blockIdx.x * kcn + koff;

    auto fill = [&](int c, int s) {            // tid 0 only
        MBARRIER_EXPECT_TX(mbf[s], STAGE_BYTES);
        const uint32_t st = sbase + s * STAGE_BYTES;
        const size_t ao = (a_tile0 + c) << 13;
        const size_t bo = (b_tile0 + c) << 14;
        bulk_g2s(st,                Ahi + ao, A_TILE_B, mbf[s]);
        bulk_g2s(st + A_TILE_B,     Alo + ao, A_TILE_B, mbf[s]);
        bulk_g2s(st + 2 * A_TILE_B, Bhi + bo, B_TILE_B, mbf[s]);
        bulk_g2s(st + 2 * A_TILE_B + B_TILE_B, Blo + bo, B_TILE_B, mbf[s]);
    };

    float acc[2][8][4];
#pragma unroll
    for (int mi = 0; mi < 2; mi++)
#pragma unroll
        for (int ni = 0; ni < 8; ni++)
#pragma unroll
            for (int f = 0; f < 4; f++) acc[mi][ni][f] = 0.f;

    if (tid == 0)
        for (int c = 0; c < NSTAGE && c < kcn_per; c++) fill(c, c);

    int ph[NSTAGE]  = {0, 0};
    int eph[NSTAGE] = {0, 0};
    for (int c = 0; c < kcn_per; c++) {
        const int s = c & 1;
        MBARRIER_WAIT_PARITY(mbf[s], ph[s]);
        ph[s] ^= 1;

        const uint32_t st = sbase + s * STAGE_BYTES;
        const uint32_t Ah = st;
        const uint32_t Al = st + A_TILE_B;
        const uint32_t Bh = st + 2 * A_TILE_B;
        const uint32_t Bl = Bh + B_TILE_B;

#pragma unroll
        for (int ks = 0; ks < 4; ks++) {
            uint32_t ah[2][4], al[2][4];
#pragma unroll
            for (int mi = 0; mi < 2; mi++) {
                uint32_t off = a_row_off[mi] + ((ks * 32 + ac) ^ a_xor);
                LDSM4(ah[mi], Ah + off);
                LDSM4(al[mi], Al + off);
            }
            const uint32_t bko = bkb + (uint32_t)ks * 8192;   // 16 k-rows
#pragma unroll
            for (int nj = 0; nj < 4; nj++) {
                uint32_t bh[4], bl[4];
                uint32_t off = bko + b_cn[nj];
                LDSM4T(bh, Bh + off);
                LDSM4T(bl, Bl + off);
#pragma unroll
                for (int mi = 0; mi < 2; mi++)
#pragma unroll
                    for (int hf = 0; hf < 2; hf++) {
                        float* ap = acc[mi][nj * 2 + hf];
                        MMA_BF16(ap, ah[mi][0], ah[mi][1], ah[mi][2], ah[mi][3],
                                 bh[hf * 2], bh[hf * 2 + 1]);
                        MMA_BF16(ap, ah[mi][0], ah[mi][1], ah[mi][2], ah[mi][3],
                                 bl[hf * 2], bl[hf * 2 + 1]);
                        MMA_BF16(ap, al[mi][0], al[mi][1], al[mi][2], al[mi][3],
                                 bh[hf * 2], bh[hf * 2 + 1]);
                    }
            }
        }
        // this warp is done reading stage s
        if (lane == 0) MBARRIER_ARRIVE(mbe[s]);
        // producer: refill stage s once all 16 warps have drained it
        if (tid == 0 && c + NSTAGE < kcn_per) {
            MBARRIER_WAIT_PARITY(mbe[s], eph[s]);
            eph[s] ^= 1;
            fill(c + NSTAGE, s);
        }
    }

    // ---- epilogue (N even everywhere -> pairwise guard ok)
    const int Kc = 1 << ksh;
    float* Cp = (OUT == 2) ? (C + (size_t)blockIdx.z * M * N) : C;
#pragma unroll
    for (int mi = 0; mi < 2; mi++) {
        const int m0 = bm + wm * 32 + mi * 16;
#pragma unroll
        for (int ni = 0; ni < 8; ni++) {
            const int n = bn + wn * 64 + ni * 8 + 2 * q;
            if (n >= N) continue;
            float b0 = 0.f, b1 = 0.f;
            if (OUT != 2 && bias) { b0 = bias[n]; b1 = bias[n + 1]; }
#pragma unroll
            for (int hf = 0; hf < 2; hf++) {
                const int m = m0 + g + hf * 8;
                float v0 = acc[mi][ni][hf * 2 + 0] + b0;
                float v1 = acc[mi][ni][hf * 2 + 1] + b1;
                if (OUT != 2 && ACT == 1) {
                    v0 = fmaxf(v0, 0.f); v1 = fmaxf(v1, 0.f);
                }
                if (OUT == 1) {
                    size_t flat = (size_t)m * N + n;
                    size_t mr = flat >> ksh;
                    int kk = (int)(flat & (Kc - 1));
                    split_store(Chi, Clo, tile_off(mr, kk, Kc >> 6), v0, v1);
                } else {
                    *(float2*)(Cp + (size_t)m * N + n) = make_float2(v0, v1);
                }
            }
        }
    }

    __syncthreads();
    if (tid == 0)
#pragma unroll
        for (int i = 0; i < NSTAGE; i++) {
            MBARRIER_INVAL(mbf[i]);
            MBARRIER_INVAL(mbe[i]);
        }
}

// ---------------------------------------------------------------------------
// Split-K reduce: sum nsplit partials, add bias, act; OUT=0 fp32, OUT=1 tiles.
// ---------------------------------------------------------------------------
template <int ACT, int OUT>
__global__ void __launch_bounds__(256)
reduce_kernel(const float* __restrict__ P, int nsplit, size_t MN,
              const float* __restrict__ bias, int nmask,
              float* __restrict__ C,
              __nv_bfloat16* __restrict__ Chi, __nv_bfloat16* __restrict__ Clo,
              int ksh)
{
    size_t f = ((size_t)blockIdx.x * 256 + threadIdx.x) * 2;
    if (f >= MN) return;
    float v0 = 0.f, v1 = 0.f;
#pragma unroll 4
    for (int z = 0; z < nsplit; z++) {
        float2 p = *(const float2*)(P + (size_t)z * MN + f);
        v0 += p.x; v1 += p.y;
    }
    if (bias) {
        int n = (int)(f & nmask);
        v0 += bias[n]; v1 += bias[n + 1];
    }
    if (ACT == 1) { v0 = fmaxf(v0, 0.f); v1 = fmaxf(v1, 0.f); }
    if (OUT == 0) {
        *(float2*)(C + f) = make_float2(v0, v1);
    } else {
        size_t mr = f >> ksh;
        int kk = (int)(f & ((1 << ksh) - 1));
        split_store(Chi, Clo, tile_off(mr, kk, (1 << ksh) >> 6), v0, v1);
    }
}

// ---------------------------------------------------------------------------
// Fused conv+SiLU+dt+scan. One CTA per (batch, head), 256 threads.
// ---------------------------------------------------------------------------
__global__ void __launch_bounds__(256)
fused_scan_kernel(const float* __restrict__ zx,
                  const float* __restrict__ conv_w,
                  const float* __restrict__ conv_b,
                  const float* __restrict__ dt_bias,
                  const float* __restrict__ A_log,
                  const float* __restrict__ Dp,
                  float* __restrict__ y)
{
    const int b = blockIdx.x;
    const int h = blockIdx.y;
    const int t = threadIdx.x;

    __shared__ float Bsh[SEQL][DSTATE];
    __shared__ float Csh[SEQL][DSTATE];
    __shared__ float xsh[SEQL][HEADDIM];
    __shared__ float dts[SEQL], dAs[SEQL];

    const float* zrow = zx + (size_t)b * SEQL * DPROJ;

    {
        const int ch  = 2048 + t;
        const int src = D_INNER + ch;
        const float w0 = conv_w[ch * 4 + 0], w1 = conv_w[ch * 4 + 1];
        const float w2 = conv_w[ch * 4 + 2], w3 = conv_w[ch * 4 + 3];
        const float bb = conv_b[ch];
        float v[SEQL];
#pragma unroll
        for (int l = 0; l < SEQL; l++) v[l] = zrow[(size_t)l * DPROJ + src];
#pragma unroll
        for (int l = 0; l < SEQL; l++) {
            float sv = bb + v[l] * w3;
            if (l >= 1) sv += v[l - 1] * w2;
            if (l >= 2) sv += v[l - 2] * w1;
            if (l >= 3) sv += v[l - 3] * w0;
            sv = sv / (1.f + expf(-sv));
            if (t < 128) Bsh[l][t] = sv;
            else         Csh[l][t - 128] = sv;
        }
    }
    if (t < HEADDIM) {
        const int ch  = h * HEADDIM + t;
        const int src = D_INNER + ch;
        const float w0 = conv_w[ch * 4 + 0], w1 = conv_w[ch * 4 + 1];
        const float w2 = conv_w[ch * 4 + 2], w3 = conv_w[ch * 4 + 3];
        const float bb = conv_b[ch];
        float v[SEQL];
#pragma unroll
        for (int l = 0; l < SEQL; l++) v[l] = zrow[(size_t)l * DPROJ + src];
#pragma unroll
        for (int l = 0; l < SEQL; l++) {
            float sv = bb + v[l] * w3;
            if (l >= 1) sv += v[l - 1] * w2;
            if (l >= 2) sv += v[l - 2] * w1;
            if (l >= 3) sv += v[l - 3] * w0;
            xsh[l][t] = sv / (1.f + expf(-sv));
        }
    }
    if (t >= 64 && t < 64 + SEQL) {
        const int l = t - 64;
        float xr = zrow[(size_t)l * DPROJ + (D_INNER + CONV_DIM) + h] + dt_bias[h];
        float dt = (xr > 20.f) ? xr : log1pf(expf(xr));
        dts[l] = dt;
        dAs[l] = expf(-expf(A_log[h]) * dt);
    }
    __syncthreads();

    const int p = t >> 2;
    const int q = t & 3;
    float st[32];
#pragma unroll
    for (int i = 0; i < 32; i++) st[i] = 0.f;
    const float Dh = Dp[h];

#pragma unroll
    for (int l = 0; l < SEQL; l++) {
        const float xv   = xsh[l][p];
        const float coef = dts[l] * xv;
        const float dAv  = dAs[l];
        float part = 0.f;
#pragma unroll
        for (int i = 0; i < 32; i++) {
            const int sidx = q + 4 * i;
            st[i] = fmaf(dAv, st[i], coef * Bsh[l][sidx]);
            part  = fmaf(st[i], Csh[l][sidx], part);
        }
        part += __shfl_down_sync(0xffffffffu, part, 2);
        part += __shfl_down_sync(0xffffffffu, part, 1);
        if (q == 0)
            y[((size_t)b * SEQL + l) * D_INNER + h * HEADDIM + p] = part + xv * Dh;
    }
}

// ---------------------------------------------------------------------------
// y = y * silu(z); y *= rsqrt(mean(y^2)+1e-5) * norm_w; emit split A-tiles.
// ---------------------------------------------------------------------------
__global__ void __launch_bounds__(256)
gated_rmsnorm_split_kernel(const float* __restrict__ ybuf,
                           const float* __restrict__ zx,
                           const float* __restrict__ norm_w,
                           __nv_bfloat16* __restrict__ hi,
                           __nv_bfloat16* __restrict__ lo)
{
    const size_t row = blockIdx.x;
    const int t = threadIdx.x;
    const int d0 = t * 8;
    const float* yb = ybuf + row * D_INNER;
    const float* zb = zx   + row * DPROJ;

    float v[8];
    float ss = 0.f;
#pragma unroll
    for (int j = 0; j < 8; j += 4) {
        float4 yv = *(const float4*)(yb + d0 + j);
        float4 zv = *(const float4*)(zb + d0 + j);
        v[j + 0] = yv.x * (zv.x / (1.f + expf(-zv.x)));
        v[j + 1] = yv.y * (zv.y / (1.f + expf(-zv.y)));
        v[j + 2] = yv.z * (zv.z / (1.f + expf(-zv.z)));
        v[j + 3] = yv.w * (zv.w / (1.f + expf(-zv.w)));
        ss = fmaf(v[j+0], v[j+0], ss); ss = fmaf(v[j+1], v[j+1], ss);
        ss = fmaf(v[j+2], v[j+2], ss); ss = fmaf(v[j+3], v[j+3], ss);
    }
#pragma unroll
    for (int o = 16; o > 0; o >>= 1)
        ss += __shfl_down_sync(0xffffffffu, ss, o);

    __shared__ float red[8];
    __shared__ float s_scale;
    if ((t & 31) == 0) red[t >> 5] = ss;
    __syncthreads();
    if (t == 0) {
        float s = 0.f;
        for (int i = 0; i < 8; i++) s += red[i];
        s_scale = rsqrtf(s / (float)D_INNER + 1e-5f);
    }
    __syncthreads();
    const float scale = s_scale;

#pragma unroll
    for (int j = 0; j < 8; j += 2) {
        int d = d0 + j;
        float v0 = v[j]     * scale * norm_w[d];
        float v1 = v[j + 1] * scale * norm_w[d + 1];
        split_store(hi, lo, tile_off(row, d, D_INNER >> 6), v0, v1);
    }
}

// ---------------------------------------------------------------------------
// Final tiny layer: out = A(256x1024) @ W(1024x2) + b. One CTA per row.
// ---------------------------------------------------------------------------
__global__ void __launch_bounds__(256)
final_kernel(const float* __restrict__ A, const float* __restrict__ W,
             const float* __restrict__ bias, float* __restrict__ out)
{
    const int m = blockIdx.x;
    const int t = threadIdx.x;
    float4 a = ((const float4*)(A + (size_t)m * 1024))[t];
    const float4 w0 = ((const float4*)W)[2 * t];
    const float4 w1 = ((const float4*)W)[2 * t + 1];
    float s0 = a.x * w0.x + a.y * w0.z + a.z * w1.x + a.w * w1.z;
    float s1 = a.x * w0.y + a.y * w0.w + a.z * w1.y + a.w * w1.w;
#pragma unroll
    for (int o = 16; o > 0; o >>= 1) {
        s0 += __shfl_down_sync(0xffffffffu, s0, o);
        s1 += __shfl_down_sync(0xffffffffu, s1, o);
    }
    __shared__ float r0[8], r1[8];
    if ((t & 31) == 0) { r0[t >> 5] = s0; r1[t >> 5] = s1; }
    __syncthreads();
    if (t == 0) {
        float a0 = 0.f, a1 = 0.f;
        for (int i = 0; i < 8; i++) { a0 += r0[i]; a1 += r1[i]; }
        out[m * 2 + 0] = a0 + bias[0];
        out[m * 2 + 1] = a1 + bias[1];
    }
}

// ---------------------------------------------------------------------------
// Host-side orchestration
// ---------------------------------------------------------------------------
struct MambaW {
    const float *in_proj, *conv_w, *conv_b, *dt_bias, *A_log, *D, *norm_w, *out_proj;
};

extern "C" void kernel_launch(void* const* d_in, const int* in_sizes, int n_in,
                              void* d_out, int out_size)
{
    const float* x      = (const float*)d_in[0];
    const float* w_in1  = (const float*)d_in[1];
    const float* b_in1  = (const float*)d_in[2];
    const float* w_in2  = (const float*)d_in[3];
    const float* b_in2  = (const float*)d_in[4];
    MambaW m1 = { (const float*)d_in[5],  (const float*)d_in[6],  (const float*)d_in[7],
                  (const float*)d_in[8],  (const float*)d_in[9],  (const float*)d_in[10],
                  (const float*)d_in[11], (const float*)d_in[12] };
    MambaW m2 = { (const float*)d_in[13], (const float*)d_in[14], (const float*)d_in[15],
                  (const float*)d_in[16], (const float*)d_in[17], (const float*)d_in[18],
                  (const float*)d_in[19], (const float*)d_in[20] };
    const float* w_out1 = (const float*)d_in[21];
    const float* b_out1 = (const float*)d_in[22];
    const float* w_out2 = (const float*)d_in[23];
    const float* b_out2 = (const float*)d_in[24];
    float* out = (float*)d_out;

    cudaFuncSetAttribute(tc_gemm_kernel<0, 0>,
                         cudaFuncAttributeMaxDynamicSharedMemorySize, TCG_SMEM);
    cudaFuncSetAttribute(tc_gemm_kernel<0, 1>,
                         cudaFuncAttributeMaxDynamicSharedMemorySize, TCG_SMEM);
    cudaFuncSetAttribute(tc_gemm_kernel<0, 2>,
                         cudaFuncAttributeMaxDynamicSharedMemorySize, TCG_SMEM);
    cudaFuncSetAttribute(tc_gemm_kernel<1, 0>,
                         cudaFuncAttributeMaxDynamicSharedMemorySize, TCG_SMEM);

    float *a, *zx, *ybuf, *part;
    __nv_bfloat16 *whi, *wlo, *p1h, *p1l, *p2h, *p2l;
    cudaGetSymbolAddress((void**)&a,    g_a);
    cudaGetSymbolAddress((void**)&zx,   g_zx);
    cudaGetSymbolAddress((void**)&ybuf, g_y);
    cudaGetSymbolAddress((void**)&part, g_part);
    cudaGetSymbolAddress((void**)&whi,  g_whi);
    cudaGetSymbolAddress((void**)&wlo,  g_wlo);
    cudaGetSymbolAddress((void**)&p1h,  g_p1hi);
    cudaGetSymbolAddress((void**)&p1l,  g_p1lo);
    cudaGetSymbolAddress((void**)&p2h,  g_p2hi);
    cudaGetSymbolAddress((void**)&p2l,  g_p2lo);

    // ---- weight preprocessing (streaming convert, no transpose)
    auto cvt = [&](const float* W, size_t off, int K, int N, int Npad) {
        convert_b_kernel<<<dim3(Npad / 256, K / 64), 256>>>(
            W, whi + off, wlo + off, K, N);
    };
    cvt(w_in1,       OFF_WIN1,    1024, 8192, 8192);
    cvt(w_in2,       OFF_WIN2,    8192, 8192, 8192);
    cvt(m1.in_proj,  OFF_M1_INP,  1024, DPROJ, 4608);
    cvt(m2.in_proj,  OFF_M2_INP,  1024, DPROJ, 4608);
    cvt(m1.out_proj, OFF_M1_OUTP, 2048, 1024, 1024);
    cvt(m2.out_proj, OFF_M2_OUTP, 2048, 1024, 1024);
    cvt(w_out1,      OFF_WOUT1,   8192, 1024, 1024);

    // ---- split x -> p1 (256 x 1024, kshift 10)
    split_a_kernel<<<(BATCH * 1024 / 4 + 255) / 256, 256>>>(x, p1h, p1l,
                                                            BATCH * 1024 / 4, 10);

    const size_t MN_256x8192  = (size_t)BATCH * 8192;
    const size_t MN_2048x1024 = (size_t)ROWS * 1024;
    const size_t MN_256x1024  = (size_t)BATCH * 1024;

    // ---- MLP in (split-K x4)
    tc_gemm_kernel<0, 2><<<dim3(32, 2, 4), 512, TCG_SMEM>>>(
        p1h, p1l, whi + OFF_WIN1, wlo + OFF_WIN1, nullptr,
        part, nullptr, nullptr, 13, 4, BATCH, 8192, 1024);
    reduce_kernel<1, 1><<<(unsigned)(MN_256x8192 / 512), 256>>>(
        part, 4, MN_256x8192, b_in1, 8191, nullptr, p2h, p2l, 13);
    tc_gemm_kernel<0, 2><<<dim3(32, 2, 4), 512, TCG_SMEM>>>(
        p2h, p2l, whi + OFF_WIN2, wlo + OFF_WIN2, nullptr,
        part, nullptr, nullptr, 10, 32, BATCH, 8192, 8192);
    reduce_kernel<0, 1><<<(unsigned)(MN_256x8192 / 512), 256>>>(
        part, 4, MN_256x8192, b_in2, 8191, nullptr, p1h, p1l, 10);

    // ---- 2x Mamba2 layers (h tiles live in p1 as (2048, 1024))
    const MambaW* layers[2] = { &m1, &m2 };
    const size_t inp_off[2]  = { OFF_M1_INP,  OFF_M2_INP };
    const size_t outp_off[2] = { OFF_M1_OUTP, OFF_M2_OUTP };
    for (int li = 0; li < 2; li++) {
        const MambaW& p = *layers[li];
        // zx = h @ in_proj (fp32 out, 288 CTAs, no split)
        tc_gemm_kernel<0, 0><<<dim3(18, 16, 1), 512, TCG_SMEM>>>(
            p1h, p1l, whi + inp_off[li], wlo + inp_off[li], nullptr,
            zx, nullptr, nullptr, 0, 16, ROWS, DPROJ, 1024);
        fused_scan_kernel<<<dim3(BATCH, NHEADS), 256>>>(
            zx, p.conv_w, p.conv_b, p.dt_bias, p.A_log, p.D, ybuf);
        gated_rmsnorm_split_kernel<<<ROWS, 256>>>(ybuf, zx, p.norm_w, p2h, p2l);
        // h = y @ out_proj: split-K x4, reduce -> p1 tiles
        int ksh_next = (li == 0) ? 10 : 13;
        tc_gemm_kernel<0, 2><<<dim3(4, 16, 4), 512, TCG_SMEM>>>(
            p2h, p2l, whi + outp_off[li], wlo + outp_off[li], nullptr,
            part, nullptr, nullptr, ksh_next, 8, ROWS, 1024, 2048);
        reduce_kernel<0, 1><<<(unsigned)(MN_2048x1024 / 512), 256>>>(
            part, 4, MN_2048x1024, nullptr, 1023, nullptr, p1h, p1l, ksh_next);
    }

    // ---- MLP out: split-K x32, reduce(relu+bias) -> fp32 a; final dot
    tc_gemm_kernel<0, 2><<<dim3(4, 2, 32), 512, TCG_SMEM>>>(
        p1h, p1l, whi + OFF_WOUT1, wlo + OFF_WOUT1, nullptr,
        part, nullptr, nullptr, 0, 4, BATCH, 1024, 8192);
    reduce_kernel<1, 0><<<(unsigned)(MN_256x1024 / 512), 256>>>(
        part, 32, MN_256x1024, b_out1, 1023, a, nullptr, nullptr, 0);
    final_kernel<<<BATCH, 256>>>(a, w_out2, b_out2, out);
}

// round 15
// speedup vs baseline: 1.1370x; 1.0192x over previous
#include <cuda_runtime.h>
#include <cuda_bf16.h>
#include <cstdint>

// ---------------------------------------------------------------------------
// Problem dimensions (fixed by the reference)
// ---------------------------------------------------------------------------
#define BATCH    256
#define SEQL     8
#define HIDD     1024            // HID
#define D_INNER  2048
#define DSTATE   128
#define NHEADS   32
#define HEADDIM  64
#define CONV_DIM 2304            // D_INNER + 2*DSTATE
#define DPROJ    4384            // 2*D_INNER + 2*DSTATE + NHEADS
#define ROWS     (BATCH * SEQL)  // 2048

// ---------------------------------------------------------------------------
// Scratch (static device buffers; no allocation allowed in kernel_launch)
// ---------------------------------------------------------------------------
__device__ float g_a   [BATCH * 8192];    // fp32 intermediate (out1 output)
__device__ float g_zx  [ROWS  * DPROJ];   // zxbcdt (2048 x 4384)
__device__ float g_y   [ROWS  * D_INNER]; // SSM output (2048 x 2048)
__device__ float g_part[8388608];         // split-K partials

// Two ping-pong split-bf16 tiled activation buffers (max 2048x2048)
#define AMAX 4194304
__device__ __nv_bfloat16 g_p1hi[AMAX];
__device__ __nv_bfloat16 g_p1lo[AMAX];
__device__ __nv_bfloat16 g_p2hi[AMAX];
__device__ __nv_bfloat16 g_p2lo[AMAX];

// Split-bf16 tiled weights. B tile = 64 k-rows x 256 n-cols, (K,N) layout,
// 512B per k-row, 16B chunks xor-swizzled by (k&7)<<4. One tile = 32KB
// contiguous; tile index = nb * (K/64) + kc. N padded to mult of 256.
#define OFF_WIN1     0ULL
#define OFF_WIN2     8388608ULL      // win1: 8192*1024
#define OFF_M1_INP   75497472ULL     // win2: 8192*8192
#define OFF_M2_INP   80216064ULL     // inproj: 4608*1024
#define OFF_M1_OUTP  84934656ULL
#define OFF_M2_OUTP  87031808ULL     // outproj: 1024*2048
#define OFF_WOUT1    89128960ULL
#define WT_TOTAL     97517568ULL     // + wout1: 1024*8192
__device__ __nv_bfloat16 g_whi[WT_TOTAL];
__device__ __nv_bfloat16 g_wlo[WT_TOTAL];

// ---------------------------------------------------------------------------
// PTX helpers
// ---------------------------------------------------------------------------
__device__ __forceinline__ uint32_t smem_u32(const void* p) {
    uint32_t a;
    asm("{ .reg .u64 t; cvta.to.shared.u64 t, %1; cvt.u32.u64 %0, t; }"
        : "=r"(a) : "l"(p));
    return a;
}

#define MBARRIER_INIT(addr, count) \
    asm volatile("mbarrier.init.shared.b64 [%0], %1;" \
                 :: "r"((uint32_t)(addr)), "r"((uint32_t)(count)) : "memory")
#define MBARRIER_INVAL(addr) \
    asm volatile("mbarrier.inval.shared.b64 [%0];" \
                 :: "r"((uint32_t)(addr)) : "memory")
#define MBARRIER_EXPECT_TX(addr, bytes) \
    asm volatile("mbarrier.arrive.expect_tx.shared.b64 _, [%0], %1;" \
                 :: "r"((uint32_t)(addr)), "r"((uint32_t)(bytes)) : "memory")
#define MBARRIER_ARRIVE(addr) \
    asm volatile("mbarrier.arrive.shared.b64 _, [%0];" \
                 :: "r"((uint32_t)(addr)) : "memory")

#define MBARRIER_WAIT_PARITY(addr, par) do {                                   \
    uint32_t _m = (uint32_t)(addr), _p = (uint32_t)(par), _d;                  \
    asm volatile(                                                              \
        "{\n\t.reg .pred p;\n\t"                                               \
        "mbarrier.try_wait.parity.acquire.cta.shared::cta.b64 p, [%1], %2;\n\t"\
        "selp.b32 %0, 1, 0, p;\n\t}"                                           \
        : "=r"(_d) : "r"(_m), "r"(_p) : "memory");                             \
    if (!_d) {                                                                 \
        asm volatile(                                                          \
            "{\n\t.reg .pred P1;\n\t"                                          \
            "WL_%=:\n\t"                                                       \
            "mbarrier.try_wait.parity.acquire.cta.shared::cta.b64 P1, [%0], %1, 0x989680;\n\t" \
            "@P1 bra.uni WD_%=;\n\t"                                           \
            "bra.uni WL_%=;\n\t"                                               \
            "WD_%=:\n\t}"                                                      \
            :: "r"(_m), "r"(_p) : "memory");                                   \
    }                                                                          \
} while (0)

__device__ __forceinline__ void bulk_g2s(uint32_t sdst, const void* gsrc,
                                         uint32_t bytes, uint32_t mbar) {
    asm volatile(
        "cp.async.bulk.shared::cluster.global.mbarrier::complete_tx::bytes "
        "[%0], [%1], %2, [%3];"
        :: "r"(sdst), "l"(gsrc), "r"(bytes), "r"(mbar) : "memory");
}

#define LDSM4(r, addr) \
    asm volatile("ldmatrix.sync.aligned.m8n8.x4.shared.b16 {%0,%1,%2,%3}, [%4];" \
                 : "=r"((r)[0]), "=r"((r)[1]), "=r"((r)[2]), "=r"((r)[3]) \
                 : "r"(addr))

#define LDSM4T(r, addr) \
    asm volatile("ldmatrix.sync.aligned.m8n8.x4.trans.shared.b16 {%0,%1,%2,%3}, [%4];" \
                 : "=r"((r)[0]), "=r"((r)[1]), "=r"((r)[2]), "=r"((r)[3]) \
                 : "r"(addr))

#define MMA_BF16(ACCP, A0, A1, A2, A3, B0, B1)                              \
    asm volatile(                                                           \
        "mma.sync.aligned.m16n8k16.row.col.f32.bf16.bf16.f32 "              \
        "{%0,%1,%2,%3}, {%4,%5,%6,%7}, {%8,%9}, {%0,%1,%2,%3};\n"           \
        : "+f"((ACCP)[0]), "+f"((ACCP)[1]), "+f"((ACCP)[2]), "+f"((ACCP)[3])\
        : "r"(A0), "r"(A1), "r"(A2), "r"(A3), "r"(B0), "r"(B1))

// A-side split-tile address: element (row mr, col kk) of an (M,Kc) operand in
// 128x64 swizzled tiles; returns offset in halves. kk must be even.
__device__ __forceinline__ size_t tile_off(size_t mr, int kk, int kc_n) {
    int mb = (int)(mr >> 7), r = (int)(mr & 127);
    int kc = kk >> 6, kl = kk & 63;
    uint32_t off = (uint32_t)(r * 128 + kl * 2);
    uint32_t sw  = off ^ ((uint32_t)(r & 7) << 4);
    return (((size_t)mb * kc_n + kc) << 13) + (sw >> 1);
}

__device__ __forceinline__ void split_store(__nv_bfloat16* hi, __nv_bfloat16* lo,
                                            size_t base, float v0, float v1) {
    __nv_bfloat16 h0 = __float2bfloat16(v0);
    __nv_bfloat16 h1 = __float2bfloat16(v1);
    *(__nv_bfloat162*)(hi + base) = __halves2bfloat162(h0, h1);
    *(__nv_bfloat162*)(lo + base) = __halves2bfloat162(
        __float2bfloat16(v0 - __bfloat162float(h0)),
        __float2bfloat16(v1 - __bfloat162float(h1)));
}

// ---------------------------------------------------------------------------
// MERGED weight preprocessing: all 7 weights in ONE launch.
// W (K,N) fp32 -> hi/lo bf16 (K,N) tiles (64k x 256n, 512B rows,
// 16B-chunk xor swizzle). Flat grid; descriptor table maps CTA -> weight.
// All 8 load pairs issued up-front (MLP=8) before convert/store.
// ---------------------------------------------------------------------------
#define NCVT 7
struct CvtTable {
    const float*       W[NCVT];
    unsigned long long off[NCVT];     // halves offset into g_whi/g_wlo
    int                K[NCVT];
    int                N[NCVT];
    int                ntx[NCVT];     // Npad/256
    int                start[NCVT + 1];
};

__global__ void __launch_bounds__(256)
convert_all_kernel(CvtTable t,
                   __nv_bfloat16* __restrict__ Ghi,
                   __nv_bfloat16* __restrict__ Glo)
{
    const int blk = blockIdx.x;
    int wi = 0;
#pragma unroll
    for (int i = 1; i < NCVT; i++)
        if (blk >= t.start[i]) wi = i;
    const int local = blk - t.start[wi];
    const int bx = local % t.ntx[wi];
    const int by = local / t.ntx[wi];

    const float* W = t.W[wi];
    const int K = t.K[wi];
    const int N = t.N[wi];
    __nv_bfloat16* Thi = Ghi + t.off[wi];
    __nv_bfloat16* Tlo = Glo + t.off[wi];

    const int tid   = threadIdx.x;
    const int nbase = bx * 256;
    const int kbase = by * 64;
    const size_t tile_h =
        ((size_t)bx * (size_t)(K >> 6) + (size_t)by) << 14;

    float4 va[8], vb[8];
#pragma unroll
    for (int i = 0; i < 8; i++) {
        int id = tid + i * 256;            // 0..2047
        int k  = id >> 5;                  // 0..63
        int ch = id & 31;                  // 0..31 (8-elem chunk)
        int n  = nbase + ch * 8;
        va[i] = make_float4(0.f, 0.f, 0.f, 0.f);
        vb[i] = va[i];
        if (n < N) {                       // N % 8 == 0 -> chunk all-or-nothing
            const float* src = W + (size_t)(kbase + k) * N + n;
            va[i] = *(const float4*)src;
            vb[i] = *(const float4*)(src + 4);
        }
    }

#pragma unroll
    for (int i = 0; i < 8; i++) {
        int id = tid + i * 256;
        int k  = id >> 5;
        int ch = id & 31;
        float vv[8] = {va[i].x, va[i].y, va[i].z, va[i].w,
                       vb[i].x, vb[i].y, vb[i].z, vb[i].w};
        uint32_t hw[4], lw[4];
#pragma unroll
        for (int j = 0; j < 4; j++) {
            __nv_bfloat16 h0 = __float2bfloat16(vv[2 * j]);
            __nv_bfloat16 h1 = __float2bfloat16(vv[2 * j + 1]);
            __nv_bfloat162 hp = __halves2bfloat162(h0, h1);
            __nv_bfloat162 lp = __halves2bfloat162(
                __float2bfloat16(vv[2 * j]     - __bfloat162float(h0)),
                __float2bfloat16(vv[2 * j + 1] - __bfloat162float(h1)));
            hw[j] = *(uint32_t*)&hp;
            lw[j] = *(uint32_t*)&lp;
        }
        uint32_t c = ((uint32_t)ch * 16) ^ (((uint32_t)k & 7) << 4);
        size_t off_h = tile_h + ((k * 512 + c) >> 1);
        *(uint4*)(Thi + off_h) = make_uint4(hw[0], hw[1], hw[2], hw[3]);
        *(uint4*)(Tlo + off_h) = make_uint4(lw[0], lw[1], lw[2], lw[3]);
    }
}

// ---------------------------------------------------------------------------
// Activation split: A (M,K) fp32 -> hi/lo bf16 A-tiles. K = 1<<kshift.
// ---------------------------------------------------------------------------
__global__ void __launch_bounds__(256)
split_a_kernel(const float* __restrict__ A,
               __nv_bfloat16* __restrict__ hi, __nv_bfloat16* __restrict__ lo,
               int n4, int kshift)
{
    int idx = blockIdx.x * 256 + threadIdx.x;
    if (idx >= n4) return;
    const int K = 1 << kshift;
    int idx4 = idx << 2;
    size_t m = (size_t)(idx4 >> kshift);
    int k = idx4 & (K - 1);
    float4 v = ((const float4*)A)[idx];
    split_store(hi, lo, tile_off(m, k,     K >> 6), v.x, v.y);
    split_store(hi, lo, tile_off(m, k + 2, K >> 6), v.z, v.w);
}

// ---------------------------------------------------------------------------
// Split-bf16 GEMM, CTA tile 128x256, 512 threads (16 warps 4Mx4N, warp 32x64).
// A tiles: (M,K) 128x64h (LDSM). B tiles: (K,N) 64x256 (LDSM.T).
// 2-stage bulk-copy pipeline with full/empty mbarrier pairs (no per-slab
// __syncthreads). Split-K via blockIdx.z.
// OUT=0: C fp32 + bias/act. OUT=1: split tiles (K'=1<<ksh) + bias/act.
// OUT=2: fp32 partial at C + z*M*N (no bias/act).
// ---------------------------------------------------------------------------
#define A_TILE_B    16384
#define B_TILE_B    32768
#define STAGE_BYTES (2 * A_TILE_B + 2 * B_TILE_B)   // 98304
#define NSTAGE      2
#define TCG_SMEM    (NSTAGE * STAGE_BYTES)          // 196608

template <int ACT, int OUT>
__global__ void __launch_bounds__(512)
tc_gemm_kernel(const __nv_bfloat16* __restrict__ Ahi,
               const __nv_bfloat16* __restrict__ Alo,
               const __nv_bfloat16* __restrict__ Bhi,
               const __nv_bfloat16* __restrict__ Blo,
               const float* __restrict__ bias, float* __restrict__ C,
               __nv_bfloat16* __restrict__ Chi, __nv_bfloat16* __restrict__ Clo,
               int ksh, int kcn_per, int M, int N, int K)
{
    extern __shared__ char dsm[];
    __shared__ uint64_t mbar_f[NSTAGE];    // full  (tx-count)
    __shared__ uint64_t mbar_e[NSTAGE];    // empty (16 warp arrivals)

    const uint32_t sbase = smem_u32(dsm);
    uint32_t mbf[NSTAGE], mbe[NSTAGE];
#pragma unroll
    for (int i = 0; i < NSTAGE; i++) {
        mbf[i] = smem_u32(&mbar_f[i]);
        mbe[i] = smem_u32(&mbar_e[i]);
    }

    const int tid  = threadIdx.x;
    const int lane = tid & 31;
    const int warp = tid >> 5;
    const int wm   = warp >> 2;                // 0..3 (M dir)
    const int wn   = warp & 3;                 // 0..3 (N dir)
    const int bm   = blockIdx.y * 128;
    const int bn   = blockIdx.x * 256;
    const int g    = lane >> 2;
    const int q    = lane & 3;

    // A fragment addressing (128x64h tile, non-trans LDSM)
    const int ar = lane & 15;
    const int ac = (lane >> 4) * 16;
    const uint32_t a_xor = (uint32_t)(ar & 7) << 4;
    uint32_t a_row_off[2];
#pragma unroll
    for (int mi = 0; mi < 2; mi++)
        a_row_off[mi] = (uint32_t)((wm * 32 + mi * 16 + ar) * 128);

    // B fragment addressing (64x256 tile, 512B rows, LDSM.T)
    const int bk  = (lane & 7) + (((lane >> 3) & 1) << 3);   // 0..15
    const int bno = (lane >> 4) << 3;                        // 0 or 8
    const uint32_t b_xor = ((uint32_t)bk & 7) << 4;
    const uint32_t bkb   = (uint32_t)bk * 512;
    uint32_t b_cn[4];
#pragma unroll
    for (int nj = 0; nj < 4; nj++)
        b_cn[nj] = ((uint32_t)((wn * 64 + nj * 16 + bno) * 2)) ^ b_xor;

    if (tid == 0)
#pragma unroll
        for (int i = 0; i < NSTAGE; i++) {
            MBARRIER_INIT(mbf[i], 1);
            MBARRIER_INIT(mbe[i], 16);         // one arrive per warp
        }
    __syncthreads();

    const int kcn = K >> 6;
    const int koff = blockIdx.z * kcn_per;
    const size_t a_tile0 = (size_t)blockIdx.y * kcn + koff;
    const size_t b_tile0 = (size_t)blockIdx.x * kcn + koff;

    auto fill = [&](int c, int s) {            // tid 0 only
        MBARRIER_EXPECT_TX(mbf[s], STAGE_BYTES);
        const uint32_t st = sbase + s * STAGE_BYTES;
        const size_t ao = (a_tile0 + c) << 13;
        const size_t bo = (b_tile0 + c) << 14;
        bulk_g2s(st,                Ahi + ao, A_TILE_B, mbf[s]);
        bulk_g2s(st + A_TILE_B,     Alo + ao, A_TILE_B, mbf[s]);
        bulk_g2s(st + 2 * A_TILE_B, Bhi + bo, B_TILE_B, mbf[s]);
        bulk_g2s(st + 2 * A_TILE_B + B_TILE_B, Blo + bo, B_TILE_B, mbf[s]);
    };

    float acc[2][8][4];
#pragma unroll
    for (int mi = 0; mi < 2; mi++)
#pragma unroll
        for (int ni = 0; ni < 8; ni++)
#pragma unroll
            for (int f = 0; f < 4; f++) acc[mi][ni][f] = 0.f;

    if (tid == 0)
        for (int c = 0; c < NSTAGE && c < kcn_per; c++) fill(c, c);

    int ph[NSTAGE]  = {0, 0};
    int eph[NSTAGE] = {0, 0};
    for (int c = 0; c < kcn_per; c++) {
        const int s = c & 1;
        MBARRIER_WAIT_PARITY(mbf[s], ph[s]);
        ph[s] ^= 1;

        const uint32_t st = sbase + s * STAGE_BYTES;
        const uint32_t Ah = st;
        const uint32_t Al = st + A_TILE_B;
        const uint32_t Bh = st + 2 * A_TILE_B;
        const uint32_t Bl = Bh + B_TILE_B;

#pragma unroll
        for (int ks = 0; ks < 4; ks++) {
            uint32_t ah[2][4], al[2][4];
#pragma unroll
            for (int mi = 0; mi < 2; mi++) {
                uint32_t off = a_row_off[mi] + ((ks * 32 + ac) ^ a_xor);
                LDSM4(ah[mi], Ah + off);
                LDSM4(al[mi], Al + off);
            }
            const uint32_t bko = bkb + (uint32_t)ks * 8192;   // 16 k-rows
#pragma unroll
            for (int nj = 0; nj < 4; nj++) {
                uint32_t bh[4], bl[4];
                uint32_t off = bko + b_cn[nj];
                LDSM4T(bh, Bh + off);
                LDSM4T(bl, Bl + off);
#pragma unroll
                for (int mi = 0; mi < 2; mi++)
#pragma unroll
                    for (int hf = 0; hf < 2; hf++) {
                        float* ap = acc[mi][nj * 2 + hf];
                        MMA_BF16(ap, ah[mi][0], ah[mi][1], ah[mi][2], ah[mi][3],
                                 bh[hf * 2], bh[hf * 2 + 1]);
                        MMA_BF16(ap, ah[mi][0], ah[mi][1], ah[mi][2], ah[mi][3],
                                 bl[hf * 2], bl[hf * 2 + 1]);
                        MMA_BF16(ap, al[mi][0], al[mi][1], al[mi][2], al[mi][3],
                                 bh[hf * 2], bh[hf * 2 + 1]);
                    }
            }
        }
        // this warp is done reading stage s
        if (lane == 0) MBARRIER_ARRIVE(mbe[s]);
        // producer: refill stage s once all 16 warps have drained it
        if (tid == 0 && c + NSTAGE < kcn_per) {
            MBARRIER_WAIT_PARITY(mbe[s], eph[s]);
            eph[s] ^= 1;
            fill(c + NSTAGE, s);
        }
    }

    // ---- epilogue (N even everywhere -> pairwise guard ok)
    const int Kc = 1 << ksh;
    float* Cp = (OUT == 2) ? (C + (size_t)blockIdx.z * M * N) : C;
#pragma unroll
    for (int mi = 0; mi < 2; mi++) {
        const int m0 = bm + wm * 32 + mi * 16;
#pragma unroll
        for (int ni = 0; ni < 8; ni++) {
            const int n = bn + wn * 64 + ni * 8 + 2 * q;
            if (n >= N) continue;
            float b0 = 0.f, b1 = 0.f;
            if (OUT != 2 && bias) { b0 = bias[n]; b1 = bias[n + 1]; }
#pragma unroll
            for (int hf = 0; hf < 2; hf++) {
                const int m = m0 + g + hf * 8;
                float v0 = acc[mi][ni][hf * 2 + 0] + b0;
                float v1 = acc[mi][ni][hf * 2 + 1] + b1;
                if (OUT != 2 && ACT == 1) {
                    v0 = fmaxf(v0, 0.f); v1 = fmaxf(v1, 0.f);
                }
                if (OUT == 1) {
                    size_t flat = (size_t)m * N + n;
                    size_t mr = flat >> ksh;
                    int kk = (int)(flat & (Kc - 1));
                    split_store(Chi, Clo, tile_off(mr, kk, Kc >> 6), v0, v1);
                } else {
                    *(float2*)(Cp + (size_t)m * N + n) = make_float2(v0, v1);
                }
            }
        }
    }

    __syncthreads();
    if (tid == 0)
#pragma unroll
        for (int i = 0; i < NSTAGE; i++) {
            MBARRIER_INVAL(mbf[i]);
            MBARRIER_INVAL(mbe[i]);
        }
}

// ---------------------------------------------------------------------------
// Split-K reduce: sum nsplit partials, add bias, act; OUT=0 fp32, OUT=1 tiles.
// ---------------------------------------------------------------------------
template <int ACT, int OUT>
__global__ void __launch_bounds__(256)
reduce_kernel(const float* __restrict__ P, int nsplit, size_t MN,
              const float* __restrict__ bias, int nmask,
              float* __restrict__ C,
              __nv_bfloat16* __restrict__ Chi, __nv_bfloat16* __restrict__ Clo,
              int ksh)
{
    size_t f = ((size_t)blockIdx.x * 256 + threadIdx.x) * 2;
    if (f >= MN) return;
    float v0 = 0.f, v1 = 0.f;
#pragma unroll 4
    for (int z = 0; z < nsplit; z++) {
        float2 p = *(const float2*)(P + (size_t)z * MN + f);
        v0 += p.x; v1 += p.y;
    }
    if (bias) {
        int n = (int)(f & nmask);
        v0 += bias[n]; v1 += bias[n + 1];
    }
    if (ACT == 1) { v0 = fmaxf(v0, 0.f); v1 = fmaxf(v1, 0.f); }
    if (OUT == 0) {
        *(float2*)(C + f) = make_float2(v0, v1);
    } else {
        size_t mr = f >> ksh;
        int kk = (int)(f & ((1 << ksh) - 1));
        split_store(Chi, Clo, tile_off(mr, kk, (1 << ksh) >> 6), v0, v1);
    }
}

// ---------------------------------------------------------------------------
// Fused conv+SiLU+dt+scan. One CTA per (batch, head), 256 threads.
// ---------------------------------------------------------------------------
__global__ void __launch_bounds__(256)
fused_scan_kernel(const float* __restrict__ zx,
                  const float* __restrict__ conv_w,
                  const float* __restrict__ conv_b,
                  const float* __restrict__ dt_bias,
                  const float* __restrict__ A_log,
                  const float* __restrict__ Dp,
                  float* __restrict__ y)
{
    const int b = blockIdx.x;
    const int h = blockIdx.y;
    const int t = threadIdx.x;

    __shared__ float Bsh[SEQL][DSTATE];
    __shared__ float Csh[SEQL][DSTATE];
    __shared__ float xsh[SEQL][HEADDIM];
    __shared__ float dts[SEQL], dAs[SEQL];

    const float* zrow = zx + (size_t)b * SEQL * DPROJ;

    {
        const int ch  = 2048 + t;
        const int src = D_INNER + ch;
        const float w0 = conv_w[ch * 4 + 0], w1 = conv_w[ch * 4 + 1];
        const float w2 = conv_w[ch * 4 + 2], w3 = conv_w[ch * 4 + 3];
        const float bb = conv_b[ch];
        float v[SEQL];
#pragma unroll
        for (int l = 0; l < SEQL; l++) v[l] = zrow[(size_t)l * DPROJ + src];
#pragma unroll
        for (int l = 0; l < SEQL; l++) {
            float sv = bb + v[l] * w3;
            if (l >= 1) sv += v[l - 1] * w2;
            if (l >= 2) sv += v[l - 2] * w1;
            if (l >= 3) sv += v[l - 3] * w0;
            sv = sv / (1.f + expf(-sv));
            if (t < 128) Bsh[l][t] = sv;
            else         Csh[l][t - 128] = sv;
        }
    }
    if (t < HEADDIM) {
        const int ch  = h * HEADDIM + t;
        const int src = D_INNER + ch;
        const float w0 = conv_w[ch * 4 + 0], w1 = conv_w[ch * 4 + 1];
        const float w2 = conv_w[ch * 4 + 2], w3 = conv_w[ch * 4 + 3];
        const float bb = conv_b[ch];
        float v[SEQL];
#pragma unroll
        for (int l = 0; l < SEQL; l++) v[l] = zrow[(size_t)l * DPROJ + src];
#pragma unroll
        for (int l = 0; l < SEQL; l++) {
            float sv = bb + v[l] * w3;
            if (l >= 1) sv += v[l - 1] * w2;
            if (l >= 2) sv += v[l - 2] * w1;
            if (l >= 3) sv += v[l - 3] * w0;
            xsh[l][t] = sv / (1.f + expf(-sv));
        }
    }
    if (t >= 64 && t < 64 + SEQL) {
        const int l = t - 64;
        float xr = zrow[(size_t)l * DPROJ + (D_INNER + CONV_DIM) + h] + dt_bias[h];
        float dt = (xr > 20.f) ? xr : log1pf(expf(xr));
        dts[l] = dt;
        dAs[l] = expf(-expf(A_log[h]) * dt);
    }
    __syncthreads();

    const int p = t >> 2;
    const int q = t & 3;
    float st[32];
#pragma unroll
    for (int i = 0; i < 32; i++) st[i] = 0.f;
    const float Dh = Dp[h];

#pragma unroll
    for (int l = 0; l < SEQL; l++) {
        const float xv   = xsh[l][p];
        const float coef = dts[l] * xv;
        const float dAv  = dAs[l];
        float part = 0.f;
#pragma unroll
        for (int i = 0; i < 32; i++) {
            const int sidx = q + 4 * i;
            st[i] = fmaf(dAv, st[i], coef * Bsh[l][sidx]);
            part  = fmaf(st[i], Csh[l][sidx], part);
        }
        part += __shfl_down_sync(0xffffffffu, part, 2);
        part += __shfl_down_sync(0xffffffffu, part, 1);
        if (q == 0)
            y[((size_t)b * SEQL + l) * D_INNER + h * HEADDIM + p] = part + xv * Dh;
    }
}

// ---------------------------------------------------------------------------
// y = y * silu(z); y *= rsqrt(mean(y^2)+1e-5) * norm_w; emit split A-tiles.
// ---------------------------------------------------------------------------
__global__ void __launch_bounds__(256)
gated_rmsnorm_split_kernel(const float* __restrict__ ybuf,
                           const float* __restrict__ zx,
                           const float* __restrict__ norm_w,
                           __nv_bfloat16* __restrict__ hi,
                           __nv_bfloat16* __restrict__ lo)
{
    const size_t row = blockIdx.x;
    const int t = threadIdx.x;
    const int d0 = t * 8;
    const float* yb = ybuf + row * D_INNER;
    const float* zb = zx   + row * DPROJ;

    float v[8];
    float ss = 0.f;
#pragma unroll
    for (int j = 0; j < 8; j += 4) {
        float4 yv = *(const float4*)(yb + d0 + j);
        float4 zv = *(const float4*)(zb + d0 + j);
        v[j + 0] = yv.x * (zv.x / (1.f + expf(-zv.x)));
        v[j + 1] = yv.y * (zv.y / (1.f + expf(-zv.y)));
        v[j + 2] = yv.z * (zv.z / (1.f + expf(-zv.z)));
        v[j + 3] = yv.w * (zv.w / (1.f + expf(-zv.w)));
        ss = fmaf(v[j+0], v[j+0], ss); ss = fmaf(v[j+1], v[j+1], ss);
        ss = fmaf(v[j+2], v[j+2], ss); ss = fmaf(v[j+3], v[j+3], ss);
    }
#pragma unroll
    for (int o = 16; o > 0; o >>= 1)
        ss += __shfl_down_sync(0xffffffffu, ss, o);

    __shared__ float red[8];
    __shared__ float s_scale;
    if ((t & 31) == 0) red[t >> 5] = ss;
    __syncthreads();
    if (t == 0) {
        float s = 0.f;
        for (int i = 0; i < 8; i++) s += red[i];
        s_scale = rsqrtf(s / (float)D_INNER + 1e-5f);
    }
    __syncthreads();
    const float scale = s_scale;

#pragma unroll
    for (int j = 0; j < 8; j += 2) {
        int d = d0 + j;
        float v0 = v[j]     * scale * norm_w[d];
        float v1 = v[j + 1] * scale * norm_w[d + 1];
        split_store(hi, lo, tile_off(row, d, D_INNER >> 6), v0, v1);
    }
}

// ---------------------------------------------------------------------------
// Final tiny layer: out = A(256x1024) @ W(1024x2) + b. One CTA per row.
// ---------------------------------------------------------------------------
__global__ void __launch_bounds__(256)
final_kernel(const float* __restrict__ A, const float* __restrict__ W,
             const float* __restrict__ bias, float* __restrict__ out)
{
    const int m = blockIdx.x;
    const int t = threadIdx.x;
    float4 a = ((const float4*)(A + (size_t)m * 1024))[t];
    const float4 w0 = ((const float4*)W)[2 * t];
    const float4 w1 = ((const float4*)W)[2 * t + 1];
    float s0 = a.x * w0.x + a.y * w0.z + a.z * w1.x + a.w * w1.z;
    float s1 = a.x * w0.y + a.y * w0.w + a.z * w1.y + a.w * w1.w;
#pragma unroll
    for (int o = 16; o > 0; o >>= 1) {
        s0 += __shfl_down_sync(0xffffffffu, s0, o);
        s1 += __shfl_down_sync(0xffffffffu, s1, o);
    }
    __shared__ float r0[8], r1[8];
    if ((t & 31) == 0) { r0[t >> 5] = s0; r1[t >> 5] = s1; }
    __syncthreads();
    if (t == 0) {
        float a0 = 0.f, a1 = 0.f;
        for (int i = 0; i < 8; i++) { a0 += r0[i]; a1 += r1[i]; }
        out[m * 2 + 0] = a0 + bias[0];
        out[m * 2 + 1] = a1 + bias[1];
    }
}

// ---------------------------------------------------------------------------
// Host-side orchestration
// ---------------------------------------------------------------------------
struct MambaW {
    const float *in_proj, *conv_w, *conv_b, *dt_bias, *A_log, *D, *norm_w, *out_proj;
};

extern "C" void kernel_launch(void* const* d_in, const int* in_sizes, int n_in,
                              void* d_out, int out_size)
{
    const float* x      = (const float*)d_in[0];
    const float* w_in1  = (const float*)d_in[1];
    const float* b_in1  = (const float*)d_in[2];
    const float* w_in2  = (const float*)d_in[3];
    const float* b_in2  = (const float*)d_in[4];
    MambaW m1 = { (const float*)d_in[5],  (const float*)d_in[6],  (const float*)d_in[7],
                  (const float*)d_in[8],  (const float*)d_in[9],  (const float*)d_in[10],
                  (const float*)d_in[11], (const float*)d_in[12] };
    MambaW m2 = { (const float*)d_in[13], (const float*)d_in[14], (const float*)d_in[15],
                  (const float*)d_in[16], (const float*)d_in[17], (const float*)d_in[18],
                  (const float*)d_in[19], (const float*)d_in[20] };
    const float* w_out1 = (const float*)d_in[21];
    const float* b_out1 = (const float*)d_in[22];
    const float* w_out2 = (const float*)d_in[23];
    const float* b_out2 = (const float*)d_in[24];
    float* out = (float*)d_out;

    cudaFuncSetAttribute(tc_gemm_kernel<0, 0>,
                         cudaFuncAttributeMaxDynamicSharedMemorySize, TCG_SMEM);
    cudaFuncSetAttribute(tc_gemm_kernel<0, 1>,
                         cudaFuncAttributeMaxDynamicSharedMemorySize, TCG_SMEM);
    cudaFuncSetAttribute(tc_gemm_kernel<0, 2>,
                         cudaFuncAttributeMaxDynamicSharedMemorySize, TCG_SMEM);
    cudaFuncSetAttribute(tc_gemm_kernel<1, 0>,
                         cudaFuncAttributeMaxDynamicSharedMemorySize, TCG_SMEM);

    float *a, *zx, *ybuf, *part;
    __nv_bfloat16 *whi, *wlo, *p1h, *p1l, *p2h, *p2l;
    cudaGetSymbolAddress((void**)&a,    g_a);
    cudaGetSymbolAddress((void**)&zx,   g_zx);
    cudaGetSymbolAddress((void**)&ybuf, g_y);
    cudaGetSymbolAddress((void**)&part, g_part);
    cudaGetSymbolAddress((void**)&whi,  g_whi);
    cudaGetSymbolAddress((void**)&wlo,  g_wlo);
    cudaGetSymbolAddress((void**)&p1h,  g_p1hi);
    cudaGetSymbolAddress((void**)&p1l,  g_p1lo);
    cudaGetSymbolAddress((void**)&p2h,  g_p2hi);
    cudaGetSymbolAddress((void**)&p2l,  g_p2lo);

    // ---- weight preprocessing: ONE merged launch for all 7 weights
    {
        CvtTable t;
        const float* Ws[NCVT] = { w_in1, w_in2, m1.in_proj, m2.in_proj,
                                  m1.out_proj, m2.out_proj, w_out1 };
        const unsigned long long offs[NCVT] = {
            OFF_WIN1, OFF_WIN2, OFF_M1_INP, OFF_M2_INP,
            OFF_M1_OUTP, OFF_M2_OUTP, OFF_WOUT1 };
        const int Ks[NCVT]    = { 1024, 8192, 1024, 1024, 2048, 2048, 8192 };
        const int Ns[NCVT]    = { 8192, 8192, DPROJ, DPROJ, 1024, 1024, 1024 };
        const int Npads[NCVT] = { 8192, 8192, 4608, 4608, 1024, 1024, 1024 };
        int acc_start = 0;
        for (int i = 0; i < NCVT; i++) {
            t.W[i]   = Ws[i];
            t.off[i] = offs[i];
            t.K[i]   = Ks[i];
            t.N[i]   = Ns[i];
            t.ntx[i] = Npads[i] / 256;
            t.start[i] = acc_start;
            acc_start += (Npads[i] / 256) * (Ks[i] / 64);
        }
        t.start[NCVT] = acc_start;
        convert_all_kernel<<<acc_start, 256>>>(t, whi, wlo);
    }

    // ---- split x -> p1 (256 x 1024, kshift 10)
    split_a_kernel<<<(BATCH * 1024 / 4 + 255) / 256, 256>>>(x, p1h, p1l,
                                                            BATCH * 1024 / 4, 10);

    const size_t MN_256x8192  = (size_t)BATCH * 8192;
    const size_t MN_2048x1024 = (size_t)ROWS * 1024;
    const size_t MN_256x1024  = (size_t)BATCH * 1024;

    // ---- MLP in (split-K x4)
    tc_gemm_kernel<0, 2><<<dim3(32, 2, 4), 512, TCG_SMEM>>>(
        p1h, p1l, whi + OFF_WIN1, wlo + OFF_WIN1, nullptr,
        part, nullptr, nullptr, 13, 4, BATCH, 8192, 1024);
    reduce_kernel<1, 1><<<(unsigned)(MN_256x8192 / 512), 256>>>(
        part, 4, MN_256x8192, b_in1, 8191, nullptr, p2h, p2l, 13);
    tc_gemm_kernel<0, 2><<<dim3(32, 2, 4), 512, TCG_SMEM>>>(
        p2h, p2l, whi + OFF_WIN2, wlo + OFF_WIN2, nullptr,
        part, nullptr, nullptr, 10, 32, BATCH, 8192, 8192);
    reduce_kernel<0, 1><<<(unsigned)(MN_256x8192 / 512), 256>>>(
        part, 4, MN_256x8192, b_in2, 8191, nullptr, p1h, p1l, 10);

    // ---- 2x Mamba2 layers (h tiles live in p1 as (2048, 1024))
    const MambaW* layers[2] = { &m1, &m2 };
    const size_t inp_off[2]  = { OFF_M1_INP,  OFF_M2_INP };
    const size_t outp_off[2] = { OFF_M1_OUTP, OFF_M2_OUTP };
    for (int li = 0; li < 2; li++) {
        const MambaW& p = *layers[li];
        // zx = h @ in_proj (fp32 out, 288 CTAs, no split)
        tc_gemm_kernel<0, 0><<<dim3(18, 16, 1), 512, TCG_SMEM>>>(
            p1h, p1l, whi + inp_off[li], wlo + inp_off[li], nullptr,
            zx, nullptr, nullptr, 0, 16, ROWS, DPROJ, 1024);
        fused_scan_kernel<<<dim3(BATCH, NHEADS), 256>>>(
            zx, p.conv_w, p.conv_b, p.dt_bias, p.A_log, p.D, ybuf);
        gated_rmsnorm_split_kernel<<<ROWS, 256>>>(ybuf, zx, p.norm_w, p2h, p2l);
        // h = y @ out_proj: split-K x4, reduce -> p1 tiles
        int ksh_next = (li == 0) ? 10 : 13;
        tc_gemm_kernel<0, 2><<<dim3(4, 16, 4), 512, TCG_SMEM>>>(
            p2h, p2l, whi + outp_off[li], wlo + outp_off[li], nullptr,
            part, nullptr, nullptr, ksh_next, 8, ROWS, 1024, 2048);
        reduce_kernel<0, 1><<<(unsigned)(MN_2048x1024 / 512), 256>>>(
            part, 4, MN_2048x1024, nullptr, 1023, nullptr, p1h, p1l, ksh_next);
    }

    // ---- MLP out: split-K x32, reduce(relu+bias) -> fp32 a; final dot
    tc_gemm_kernel<0, 2><<<dim3(4, 2, 32), 512, TCG_SMEM>>>(
        p1h, p1l, whi + OFF_WOUT1, wlo + OFF_WOUT1, nullptr,
        part, nullptr, nullptr, 0, 4, BATCH, 1024, 8192);
    reduce_kernel<1, 0><<<(unsigned)(MN_256x1024 / 512), 256>>>(
        part, 32, MN_256x1024, b_out1, 1023, a, nullptr, nullptr, 0);
    final_kernel<<<BATCH, 256>>>(a, w_out2, b_out2, out);
}